// round 10
// baseline (speedup 1.0000x reference)
#include <cuda_runtime.h>
#include <cuda_bf16.h>
#include <math_constants.h>
#include <cstdint>

#define HID  128
#define NNODE 50000
#define NEDGE 800000
#define MLPD 512

// ---------------- scratch (static device globals; no runtime alloc) ------------
__device__ __align__(16) float g_mods [(size_t)NNODE * 768];
__device__ __align__(16) float g_qkv  [(size_t)NNODE * 384];
__device__ __align__(16) float g_den  [(size_t)NNODE * 8];
__device__ __align__(16) float g_attn [(size_t)NNODE * HID];   // unnormalized Σ ex*v
__device__ __align__(16) float g_x1   [(size_t)NNODE * HID];
// pre-split activations (bf16 hi/lo)
__device__ __align__(16) __nv_bfloat16 g_xmh[(size_t)NNODE * HID];
__device__ __align__(16) __nv_bfloat16 g_xml[(size_t)NNODE * HID];
__device__ __align__(16) __nv_bfloat16 g_hh [(size_t)NNODE * MLPD];
__device__ __align__(16) __nv_bfloat16 g_hl [(size_t)NNODE * MLPD];
__device__ int g_src[NEDGE];
__device__ int g_dst[NEDGE];
__device__ int g_is32;

// transposed+split weights: WT[N][K] bf16, K contiguous
#define WOFF_ADA  0
#define WOFF_QKV  98304
#define WOFF_PROJ 147456
#define WOFF_MLP1 163840
#define WOFF_MLP2 229376
#define WTOT      294912
__device__ __align__(16) __nv_bfloat16 g_wthi[WTOT];
__device__ __align__(16) __nv_bfloat16 g_wtlo[WTOT];

// ---------------- helpers ------------------------------------------------------
__device__ __forceinline__ float siluf(float v) {
    return v / (1.0f + __expf(-v));
}
__device__ __forceinline__ float gelu_tanh(float v) {
    float v3 = v * v * v;
    float t = tanhf(0.7978845608028654f * (v + 0.044715f * v3));
    return 0.5f * v * (1.0f + t);
}
__device__ __forceinline__ uint32_t smem_u32(const void* p) {
    uint32_t a;
    asm("{ .reg .u64 t; cvta.to.shared.u64 t, %1; cvt.u32.u64 %0, t; }" : "=r"(a) : "l"(p));
    return a;
}
__device__ __forceinline__ void ldsm4(uint32_t* r, uint32_t addr) {
    asm volatile("ldmatrix.sync.aligned.m8n8.x4.shared.b16 {%0,%1,%2,%3}, [%4];"
                 : "=r"(r[0]), "=r"(r[1]), "=r"(r[2]), "=r"(r[3]) : "r"(addr));
}
__device__ __forceinline__ void mma_bf16(float* d, const uint32_t* a,
                                         uint32_t b0, uint32_t b1) {
    asm volatile(
        "mma.sync.aligned.m16n8k16.row.col.f32.bf16.bf16.f32 "
        "{%0,%1,%2,%3}, {%4,%5,%6,%7}, {%8,%9}, {%0,%1,%2,%3};"
        : "+f"(d[0]), "+f"(d[1]), "+f"(d[2]), "+f"(d[3])
        : "r"(a[0]), "r"(a[1]), "r"(a[2]), "r"(a[3]), "r"(b0), "r"(b1));
}
__device__ __forceinline__ void split_pack(float x, float y, uint32_t& hw, uint32_t& lw) {
    __nv_bfloat16 hx = __float2bfloat16(x);
    __nv_bfloat16 hy = __float2bfloat16(y);
    __nv_bfloat16 lx = __float2bfloat16(x - __bfloat162float(hx));
    __nv_bfloat16 ly = __float2bfloat16(y - __bfloat162float(hy));
    __nv_bfloat162 hp(hx, hy), lp(lx, ly);
    memcpy(&hw, &hp, 4);
    memcpy(&lw, &lp, 4);
}

// ---------------- edge-index dtype detection -----------------------------------
__global__ void detect_kernel(const void* ei_raw) {
    const long long* p = (const long long*)ei_raw;
    int bad = 0;
    for (int i = threadIdx.x; i < 256; i += blockDim.x) {
        long long v = p[i];
        if (v < 0 || v >= NNODE) bad = 1;
    }
    bad = __syncthreads_or(bad);
    if (threadIdx.x == 0) g_is32 = bad;
}

// ---------------- merged convert + accumulator init ----------------------------
__global__ void convert_init_kernel(const void* ei_raw) {
    int i = blockIdx.x * blockDim.x + threadIdx.x;
    if (i < NEDGE) {
        if (g_is32) {
            const int* p = (const int*)ei_raw;
            g_src[i] = p[i];
            g_dst[i] = p[NEDGE + i];
        } else {
            const long long* p = (const long long*)ei_raw;
            g_src[i] = (int)p[i];
            g_dst[i] = (int)p[NEDGE + i];
        }
    }
    if (i < NNODE * HID) g_attn[i] = 0.0f;
    if (i < NNODE * 8) g_den[i] = 0.0f;
}

// ---------------- weight transpose + bf16 split: W[K,N] -> WT[N,K] hi/lo -------
__global__ void wsplit_kernel(const float* __restrict__ W, int Kg, int Ng,
                              __nv_bfloat16* __restrict__ hi,
                              __nv_bfloat16* __restrict__ lo) {
    int t = blockIdx.x * blockDim.x + threadIdx.x;
    if (t >= Kg * Ng) return;
    int n = t / Kg, k = t % Kg;
    float v = W[(size_t)k * Ng + n];
    __nv_bfloat16 h = __float2bfloat16(v);
    hi[t] = h;
    lo[t] = __float2bfloat16(v - __bfloat162float(h));
}

// ---------------- LayerNorm + modulate -> bf16 hi/lo ---------------------------
__global__ void ln_mod_kernel(const float* __restrict__ X,
                              int shift_off, int scale_off,
                              __nv_bfloat16* __restrict__ out_hi,
                              __nv_bfloat16* __restrict__ out_lo) {
    int warp = (blockIdx.x * blockDim.x + threadIdx.x) >> 5;
    if (warp >= NNODE) return;
    int lane = threadIdx.x & 31;
    const float4 v = *(const float4*)(X + (size_t)warp * HID + lane * 4);
    float s  = v.x + v.y + v.z + v.w;
    float sq = v.x * v.x + v.y * v.y + v.z * v.z + v.w * v.w;
    #pragma unroll
    for (int o = 16; o > 0; o >>= 1) {
        s  += __shfl_xor_sync(0xffffffffu, s,  o);
        sq += __shfl_xor_sync(0xffffffffu, sq, o);
    }
    float mean = s * (1.0f / HID);
    float var  = sq * (1.0f / HID) - mean * mean;
    float rstd = rsqrtf(var + 1e-6f);
    const float4 sh = *(const float4*)(g_mods + (size_t)warp * 768 + shift_off + lane * 4);
    const float4 sc = *(const float4*)(g_mods + (size_t)warp * 768 + scale_off + lane * 4);
    float4 o4;
    o4.x = (v.x - mean) * rstd * (1.0f + sc.x) + sh.x;
    o4.y = (v.y - mean) * rstd * (1.0f + sc.y) + sh.y;
    o4.z = (v.z - mean) * rstd * (1.0f + sc.z) + sh.z;
    o4.w = (v.w - mean) * rstd * (1.0f + sc.w) + sh.w;
    uint32_t h0, l0, h1, l1;
    split_pack(o4.x, o4.y, h0, l0);
    split_pack(o4.z, o4.w, h1, l1);
    *(uint2*)(out_hi + (size_t)warp * HID + lane * 4) = make_uint2(h0, h1);
    *(uint2*)(out_lo + (size_t)warp * HID + lane * 4) = make_uint2(l0, l1);
}

// ---------------- bf16x3 mma.sync GEMM, 128x128 tile, 256 thr ------------------
// each warp: 32x64.  KB=32 per chunk.
// AACT: 1=silu on fp32 A.   APRE: 1=A already bf16 hi/lo ([M,K], K contiguous)
// EPI: 0=none 1=gelu->fp32  2=res+gate*(acc+bias)  3=gelu->bf16 hi/lo (Chi/Clo)
// ANORM: 1=divide A by AN[row*8 + col/16] (attention denominator)
#define SLDA 40
template<int AACT, int EPI, int ANORM, int APRE>
__global__ __launch_bounds__(256, 2)
void mma_gemm(const float* __restrict__ A,
              const __nv_bfloat16* __restrict__ AHif,
              const __nv_bfloat16* __restrict__ ALof,
              const __nv_bfloat16* __restrict__ BThi,
              const __nv_bfloat16* __restrict__ BTlo,
              const float* __restrict__ bias,
              const float* __restrict__ gate,   // row stride 768 (EPI==2)
              const float* __restrict__ res,    // row stride N   (EPI==2)
              const float* __restrict__ AN,     // row stride 8   (ANORM==1)
              float* __restrict__ C,
              __nv_bfloat16* __restrict__ Chi,  // EPI==3
              __nv_bfloat16* __restrict__ Clo,  // EPI==3
              int M, int N, int K) {
    __shared__ __nv_bfloat16 Ahi[128][SLDA], Alo[128][SLDA];
    __shared__ __nv_bfloat16 Bhi[128][SLDA], Blo[128][SLDA];

    const int tid  = threadIdx.x;
    const int lane = tid & 31;
    const int w    = tid >> 5;
    const int row0 = blockIdx.y * 128;
    const int col0 = blockIdx.x * 128;
    const int wr   = (w >> 1) * 32;   // warp row in tile
    const int wc   = (w & 1) * 64;    // warp col in tile

    float acc[2][8][4];
    #pragma unroll
    for (int i = 0; i < 2; i++)
        #pragma unroll
        for (int j = 0; j < 8; j++)
            #pragma unroll
            for (int q = 0; q < 4; q++) acc[i][j][q] = 0.0f;

    const uint32_t a_base = smem_u32(&Ahi[0][0]);
    const uint32_t al_rel = (uint32_t)((char*)&Alo[0][0] - (char*)&Ahi[0][0]);
    const uint32_t b_base = smem_u32(&Bhi[0][0]);
    const uint32_t bl_rel = (uint32_t)((char*)&Blo[0][0] - (char*)&Bhi[0][0]);

    const int a_row_l = wr + (lane & 15);
    const int a_col_l = (lane >> 4) * 8;
    const int b_row_l = wc + ((lane >> 4) & 1) * 8 + (lane & 7);
    const int b_col_l = ((lane >> 3) & 1) * 8;

    const int nchunk = K >> 5;
    for (int ch = 0; ch < nchunk; ch++) {
        const int k0 = ch * 32;
        // ---- A fill ----
        if (APRE == 1) {
            // pure copy from pre-split bf16 hi/lo [M, K]
            #pragma unroll
            for (int i = 0; i < 2; i++) {
                int idx = i * 256 + tid;       // 512 uint4 slots
                int r = idx >> 2, cc = idx & 3;
                int gr = row0 + r;
                uint4 vh = make_uint4(0u, 0u, 0u, 0u), vl = vh;
                if (gr < M) {
                    const size_t so = (size_t)gr * K + k0 + cc * 8;
                    vh = *(const uint4*)(AHif + so);
                    vl = *(const uint4*)(ALof + so);
                }
                *(uint4*)&Ahi[r][cc * 8] = vh;
                *(uint4*)&Alo[r][cc * 8] = vl;
            }
        } else {
            // fp32 load + optional silu/norm + split
            #pragma unroll
            for (int i = 0; i < 4; i++) {
                int idx = i * 256 + tid;       // 1024 float4 slots
                int r = idx >> 3, c4 = idx & 7;
                int gr = row0 + r;
                float4 v = make_float4(0.f, 0.f, 0.f, 0.f);
                if (gr < M) v = *(const float4*)(A + (size_t)gr * K + k0 + c4 * 4);
                if (AACT == 1) {
                    v.x = siluf(v.x); v.y = siluf(v.y);
                    v.z = siluf(v.z); v.w = siluf(v.w);
                }
                if (ANORM == 1) {
                    float d = (gr < M) ? AN[(size_t)gr * 8 + ((k0 + c4 * 4) >> 4)] : 0.0f;
                    float wn = (d > 0.0f) ? (1.0f / d) : 0.0f;
                    v.x *= wn; v.y *= wn; v.z *= wn; v.w *= wn;
                }
                uint32_t h0, l0, h1, l1;
                split_pack(v.x, v.y, h0, l0);
                split_pack(v.z, v.w, h1, l1);
                *(uint2*)&Ahi[r][c4 * 4] = make_uint2(h0, h1);
                *(uint2*)&Alo[r][c4 * 4] = make_uint2(l0, l1);
            }
        }
        // ---- B fill: 128 n-rows x 32 bf16 from pre-split WT ----
        #pragma unroll
        for (int i = 0; i < 2; i++) {
            int idx = i * 256 + tid;       // 512 uint4 slots
            int r = idx >> 2, cc = idx & 3;
            const size_t so = (size_t)(col0 + r) * K + k0 + cc * 8;
            *(uint4*)&Bhi[r][cc * 8] = *(const uint4*)(BThi + so);
            *(uint4*)&Blo[r][cc * 8] = *(const uint4*)(BTlo + so);
        }
        __syncthreads();

        #pragma unroll
        for (int ks = 0; ks < 2; ks++) {
            uint32_t ah[2][4], al[2][4];
            #pragma unroll
            for (int mt = 0; mt < 2; mt++) {
                uint32_t off = (uint32_t)(((a_row_l + mt * 16) * SLDA + a_col_l + ks * 16) * 2);
                ldsm4(ah[mt], a_base + off);
                ldsm4(al[mt], a_base + off + al_rel);
            }
            #pragma unroll
            for (int np = 0; np < 4; np++) {
                uint32_t bh[4], bl[4];
                uint32_t off = (uint32_t)(((b_row_l + np * 16) * SLDA + b_col_l + ks * 16) * 2);
                ldsm4(bh, b_base + off);
                ldsm4(bl, b_base + off + bl_rel);
                #pragma unroll
                for (int mt = 0; mt < 2; mt++) {
                    mma_bf16(acc[mt][np * 2],     ah[mt], bh[0], bh[1]);
                    mma_bf16(acc[mt][np * 2],     ah[mt], bl[0], bl[1]);
                    mma_bf16(acc[mt][np * 2],     al[mt], bh[0], bh[1]);
                    mma_bf16(acc[mt][np * 2 + 1], ah[mt], bh[2], bh[3]);
                    mma_bf16(acc[mt][np * 2 + 1], ah[mt], bl[2], bl[3]);
                    mma_bf16(acc[mt][np * 2 + 1], al[mt], bh[2], bh[3]);
                }
            }
        }
        __syncthreads();
    }

    // ---- epilogue: direct to global, fragment layout ----
    #pragma unroll
    for (int mt = 0; mt < 2; mt++) {
        #pragma unroll
        for (int nt = 0; nt < 8; nt++) {
            int gc = col0 + wc + nt * 8 + (lane & 3) * 2;
            #pragma unroll
            for (int g = 0; g < 2; g++) {
                int gr = row0 + wr + mt * 16 + (lane >> 2) + g * 8;
                if (gr < M) {
                    float vx = acc[mt][nt][g * 2];
                    float vy = acc[mt][nt][g * 2 + 1];
                    if (bias != nullptr) {
                        float2 b2 = *(const float2*)(bias + gc);
                        vx += b2.x; vy += b2.y;
                    }
                    if (EPI == 1 || EPI == 3) {
                        vx = gelu_tanh(vx); vy = gelu_tanh(vy);
                    } else if (EPI == 2) {
                        float2 g2 = *(const float2*)(gate + (size_t)gr * 768 + gc);
                        float2 r2 = *(const float2*)(res + (size_t)gr * N + gc);
                        vx = r2.x + g2.x * vx;
                        vy = r2.y + g2.y * vy;
                    }
                    if (EPI == 3) {
                        uint32_t hw, lw;
                        split_pack(vx, vy, hw, lw);
                        *(uint32_t*)(Chi + (size_t)gr * N + gc) = hw;
                        *(uint32_t*)(Clo + (size_t)gr * N + gc) = lw;
                    } else {
                        *(float2*)(C + (size_t)gr * N + gc) = make_float2(vx, vy);
                    }
                }
            }
        }
    }
}

// ---------------- single-pass edge attention -----------------------------------
// one warp per edge; head h = lane>>2.  Accumulates UNNORMALIZED ex*v into
// g_attn and ex into g_den; division by den happens in the proj GEMM A-fill.
__global__ void edge_attn_kernel() {
    int e = (blockIdx.x * blockDim.x + threadIdx.x) >> 5;
    if (e >= NEDGE) return;
    int lane = threadIdx.x & 31;
    int src = g_src[e];
    int dst = g_dst[e];
    const float4 q = *(const float4*)(g_qkv + (size_t)dst * 384 + lane * 4);
    const float4 k = *(const float4*)(g_qkv + (size_t)src * 384 + 128 + lane * 4);
    float p = q.x * k.x + q.y * k.y + q.z * k.z + q.w * k.w;
    p += __shfl_xor_sync(0xffffffffu, p, 1);
    p += __shfl_xor_sync(0xffffffffu, p, 2);   // all 4 lanes of head have full dot
    float ex = __expf(p * 0.25f);              // / sqrt(16)
    const float4 v = *(const float4*)(g_qkv + (size_t)src * 384 + 256 + lane * 4);
    float* pd = g_attn + (size_t)dst * HID + lane * 4;
    asm volatile("red.global.add.v4.f32 [%0], {%1, %2, %3, %4};"
                 :: "l"(pd), "f"(v.x * ex), "f"(v.y * ex), "f"(v.z * ex), "f"(v.w * ex)
                 : "memory");
    if ((lane & 3) == 0)
        atomicAdd(&g_den[(size_t)dst * 8 + (lane >> 2)], ex);
}

// ---------------- launch -------------------------------------------------------
static inline int cdiv(int a, int b) { return (a + b - 1) / b; }

extern "C" void kernel_launch(void* const* d_in, const int* in_sizes, int n_in,
                              void* d_out, int out_size) {
    const float* x      = (const float*)d_in[0];
    const void*  ei     = d_in[1];                 // int32 or int64 (detected)
    const float* c      = (const float*)d_in[2];
    const float* w_qkv  = (const float*)d_in[3];
    const float* w_proj = (const float*)d_in[4];
    const float* b_proj = (const float*)d_in[5];
    const float* w_mlp1 = (const float*)d_in[6];
    const float* b_mlp1 = (const float*)d_in[7];
    const float* w_mlp2 = (const float*)d_in[8];
    const float* b_mlp2 = (const float*)d_in[9];
    const float* w_ada  = (const float*)d_in[10];
    const float* b_ada  = (const float*)d_in[11];
    float*       out    = (float*)d_out;

    float *mods, *qkv, *x1, *attn, *den;
    __nv_bfloat16 *wthi, *wtlo, *xmh, *xml, *hh, *hl;
    cudaGetSymbolAddress((void**)&mods, g_mods);
    cudaGetSymbolAddress((void**)&qkv,  g_qkv);
    cudaGetSymbolAddress((void**)&x1,   g_x1);
    cudaGetSymbolAddress((void**)&attn, g_attn);
    cudaGetSymbolAddress((void**)&den,  g_den);
    cudaGetSymbolAddress((void**)&wthi, g_wthi);
    cudaGetSymbolAddress((void**)&wtlo, g_wtlo);
    cudaGetSymbolAddress((void**)&xmh,  g_xmh);
    cudaGetSymbolAddress((void**)&xml,  g_xml);
    cudaGetSymbolAddress((void**)&hh,   g_hh);
    cudaGetSymbolAddress((void**)&hl,   g_hl);

    const int MB = cdiv(NNODE, 128);

    // launches 0-3 (internal harness launch shifts capture; ncu -s5 grabs idx 4)
    detect_kernel<<<1, 256>>>(ei);                                                                      // 0
    convert_init_kernel<<<cdiv(NNODE * HID, 256), 256>>>(ei);                                           // 1
    wsplit_kernel<<<cdiv(128 * 768, 256), 256>>>(w_ada, 128, 768, wthi + WOFF_ADA, wtlo + WOFF_ADA);    // 2
    wsplit_kernel<<<cdiv(128 * 384, 256), 256>>>(w_qkv, 128, 384, wthi + WOFF_QKV, wtlo + WOFF_QKV);    // 3

    // mods = silu(c) @ w_ada + b_ada            [N, 768]      launch #4 (ncu target)
    mma_gemm<1, 0, 0, 0><<<dim3(768 / 128, MB), 256>>>(
        c, nullptr, nullptr, wthi + WOFF_ADA, wtlo + WOFF_ADA, b_ada,
        nullptr, nullptr, nullptr, mods, nullptr, nullptr, NNODE, 768, HID);

    // remaining weight splits
    wsplit_kernel<<<cdiv(128 * 128, 256), 256>>>(w_proj, 128, 128, wthi + WOFF_PROJ, wtlo + WOFF_PROJ);
    wsplit_kernel<<<cdiv(128 * 512, 256), 256>>>(w_mlp1, 128, 512, wthi + WOFF_MLP1, wtlo + WOFF_MLP1);
    wsplit_kernel<<<cdiv(512 * 128, 256), 256>>>(w_mlp2, 512, 128, wthi + WOFF_MLP2, wtlo + WOFF_MLP2);

    // xmod = modulate(LN(x), sh_msa, sc_msa) -> bf16 hi/lo
    ln_mod_kernel<<<cdiv(NNODE * 32, 256), 256>>>(x, 0, 128, xmh, xml);

    // qkv = xmod @ w_qkv                         [N, 384]
    mma_gemm<0, 0, 0, 1><<<dim3(384 / 128, MB), 256>>>(
        nullptr, xmh, xml, wthi + WOFF_QKV, wtlo + WOFF_QKV, nullptr,
        nullptr, nullptr, nullptr, qkv, nullptr, nullptr, NNODE, 384, HID);

    // graph attention: single pass (unnormalized aggregate + denominators)
    edge_attn_kernel<<<cdiv(NEDGE * 32, 256), 256>>>();

    // x1 = x + g_msa * ((attn/den) @ w_proj + b_proj)   (ANORM divides by den)
    mma_gemm<0, 2, 1, 0><<<dim3(1, MB), 256>>>(
        attn, nullptr, nullptr, wthi + WOFF_PROJ, wtlo + WOFF_PROJ, b_proj,
        mods + 256, x, den, x1, nullptr, nullptr, NNODE, HID, HID);

    // hmod = modulate(LN(x1), sh_mlp, sc_mlp) -> bf16 hi/lo (reuse xmh/xml)
    ln_mod_kernel<<<cdiv(NNODE * 32, 256), 256>>>(x1, 384, 512, xmh, xml);

    // h = gelu(hmod @ w_mlp1 + b_mlp1) -> bf16 hi/lo        [N, 512]
    mma_gemm<0, 3, 0, 1><<<dim3(MLPD / 128, MB), 256>>>(
        nullptr, xmh, xml, wthi + WOFF_MLP1, wtlo + WOFF_MLP1, b_mlp1,
        nullptr, nullptr, nullptr, nullptr, hh, hl, NNODE, MLPD, HID);

    // out = x1 + g_mlp * (h @ w_mlp2 + b_mlp2)
    mma_gemm<0, 2, 0, 1><<<dim3(1, MB), 256>>>(
        nullptr, hh, hl, wthi + WOFF_MLP2, wtlo + WOFF_MLP2, b_mlp2,
        mods + 640, x1, nullptr, out, nullptr, nullptr, NNODE, HID, MLPD);
}

// round 11
// speedup vs baseline: 1.1920x; 1.1920x over previous
#include <cuda_runtime.h>
#include <cuda_bf16.h>
#include <math_constants.h>
#include <cstdint>

#define HID  128
#define NNODE 50000
#define NEDGE 800000
#define MLPD 512

// ---------------- scratch (static device globals; no runtime alloc) ------------
__device__ __align__(16) float g_mods [(size_t)NNODE * 768];
__device__ __align__(16) float g_qkv  [(size_t)NNODE * 384];
__device__ __align__(16) float g_den  [(size_t)NNODE * 8];
__device__ __align__(16) float g_attn [(size_t)NNODE * HID];   // unnormalized Σ ex*v
__device__ __align__(16) float g_x1   [(size_t)NNODE * HID];
// pre-split activations (bf16 hi/lo) — reused sequentially:
// silu(c) -> ada | ln1 -> qkv | attn/den -> proj | ln2 -> mlp1
__device__ __align__(16) __nv_bfloat16 g_xmh[(size_t)NNODE * HID];
__device__ __align__(16) __nv_bfloat16 g_xml[(size_t)NNODE * HID];
__device__ __align__(16) __nv_bfloat16 g_hh [(size_t)NNODE * MLPD];
__device__ __align__(16) __nv_bfloat16 g_hl [(size_t)NNODE * MLPD];
__device__ int g_src[NEDGE];
__device__ int g_dst[NEDGE];
__device__ int g_is32;

// transposed+split weights: WT[N][K] bf16, K contiguous
#define WOFF_ADA  0
#define WOFF_QKV  98304
#define WOFF_PROJ 147456
#define WOFF_MLP1 163840
#define WOFF_MLP2 229376
#define WTOT      294912
__device__ __align__(16) __nv_bfloat16 g_wthi[WTOT];
__device__ __align__(16) __nv_bfloat16 g_wtlo[WTOT];

// ---------------- helpers ------------------------------------------------------
__device__ __forceinline__ float siluf(float v) {
    return v / (1.0f + __expf(-v));
}
__device__ __forceinline__ float gelu_tanh(float v) {
    float v3 = v * v * v;
    float t = tanhf(0.7978845608028654f * (v + 0.044715f * v3));
    return 0.5f * v * (1.0f + t);
}
__device__ __forceinline__ uint32_t smem_u32(const void* p) {
    uint32_t a;
    asm("{ .reg .u64 t; cvta.to.shared.u64 t, %1; cvt.u32.u64 %0, t; }" : "=r"(a) : "l"(p));
    return a;
}
__device__ __forceinline__ void ldsm4(uint32_t* r, uint32_t addr) {
    asm volatile("ldmatrix.sync.aligned.m8n8.x4.shared.b16 {%0,%1,%2,%3}, [%4];"
                 : "=r"(r[0]), "=r"(r[1]), "=r"(r[2]), "=r"(r[3]) : "r"(addr));
}
__device__ __forceinline__ void mma_bf16(float* d, const uint32_t* a,
                                         uint32_t b0, uint32_t b1) {
    asm volatile(
        "mma.sync.aligned.m16n8k16.row.col.f32.bf16.bf16.f32 "
        "{%0,%1,%2,%3}, {%4,%5,%6,%7}, {%8,%9}, {%0,%1,%2,%3};"
        : "+f"(d[0]), "+f"(d[1]), "+f"(d[2]), "+f"(d[3])
        : "r"(a[0]), "r"(a[1]), "r"(a[2]), "r"(a[3]), "r"(b0), "r"(b1));
}
__device__ __forceinline__ void split_pack(float x, float y, uint32_t& hw, uint32_t& lw) {
    __nv_bfloat16 hx = __float2bfloat16(x);
    __nv_bfloat16 hy = __float2bfloat16(y);
    __nv_bfloat16 lx = __float2bfloat16(x - __bfloat162float(hx));
    __nv_bfloat16 ly = __float2bfloat16(y - __bfloat162float(hy));
    __nv_bfloat162 hp(hx, hy), lp(lx, ly);
    memcpy(&hw, &hp, 4);
    memcpy(&lw, &lp, 4);
}
__device__ __forceinline__ void cpa16(uint32_t dst, const void* src, bool valid) {
    int sz = valid ? 16 : 0;
    asm volatile("cp.async.cg.shared.global [%0], [%1], 16, %2;"
                 :: "r"(dst), "l"(src), "r"(sz));
}

// ---------------- edge-index dtype detection -----------------------------------
__global__ void detect_kernel(const void* ei_raw) {
    const long long* p = (const long long*)ei_raw;
    int bad = 0;
    for (int i = threadIdx.x; i < 256; i += blockDim.x) {
        long long v = p[i];
        if (v < 0 || v >= NNODE) bad = 1;
    }
    bad = __syncthreads_or(bad);
    if (threadIdx.x == 0) g_is32 = bad;
}

// ---------------- merged convert + accumulator init ----------------------------
__global__ void convert_init_kernel(const void* ei_raw) {
    int i = blockIdx.x * blockDim.x + threadIdx.x;
    if (i < NEDGE) {
        if (g_is32) {
            const int* p = (const int*)ei_raw;
            g_src[i] = p[i];
            g_dst[i] = p[NEDGE + i];
        } else {
            const long long* p = (const long long*)ei_raw;
            g_src[i] = (int)p[i];
            g_dst[i] = (int)p[NEDGE + i];
        }
    }
    if (i < NNODE * HID) g_attn[i] = 0.0f;
    if (i < NNODE * 8) g_den[i] = 0.0f;
}

// ---------------- ALL weight transposes + bf16 splits in one kernel ------------
__global__ void wsplit_all_kernel(const float* __restrict__ w_ada,
                                  const float* __restrict__ w_qkv,
                                  const float* __restrict__ w_proj,
                                  const float* __restrict__ w_mlp1,
                                  const float* __restrict__ w_mlp2) {
    int t = blockIdx.x * blockDim.x + threadIdx.x;
    if (t >= WTOT) return;
    const float* W;
    int Kg, Ng, l;
    if (t < WOFF_QKV)       { W = w_ada;  Kg = 128; Ng = 768; l = t - WOFF_ADA; }
    else if (t < WOFF_PROJ) { W = w_qkv;  Kg = 128; Ng = 384; l = t - WOFF_QKV; }
    else if (t < WOFF_MLP1) { W = w_proj; Kg = 128; Ng = 128; l = t - WOFF_PROJ; }
    else if (t < WOFF_MLP2) { W = w_mlp1; Kg = 128; Ng = 512; l = t - WOFF_MLP1; }
    else                    { W = w_mlp2; Kg = 512; Ng = 128; l = t - WOFF_MLP2; }
    int n = l / Kg, k = l % Kg;
    float v = W[(size_t)k * Ng + n];
    __nv_bfloat16 h = __float2bfloat16(v);
    g_wthi[t] = h;
    g_wtlo[t] = __float2bfloat16(v - __bfloat162float(h));
}

// ---------------- silu(c) -> bf16 hi/lo ----------------------------------------
__global__ void silu_split_kernel(const float* __restrict__ c,
                                  __nv_bfloat16* __restrict__ hi,
                                  __nv_bfloat16* __restrict__ lo) {
    int t4 = blockIdx.x * blockDim.x + threadIdx.x;
    if (t4 >= NNODE * HID / 4) return;
    float4 v = ((const float4*)c)[t4];
    v.x = siluf(v.x); v.y = siluf(v.y); v.z = siluf(v.z); v.w = siluf(v.w);
    uint32_t h0, l0, h1, l1;
    split_pack(v.x, v.y, h0, l0);
    split_pack(v.z, v.w, h1, l1);
    *(uint2*)(hi + (size_t)t4 * 4) = make_uint2(h0, h1);
    *(uint2*)(lo + (size_t)t4 * 4) = make_uint2(l0, l1);
}

// ---------------- attn/den -> bf16 hi/lo ---------------------------------------
__global__ void attn_norm_split_kernel(__nv_bfloat16* __restrict__ hi,
                                       __nv_bfloat16* __restrict__ lo) {
    int t4 = blockIdx.x * blockDim.x + threadIdx.x;
    if (t4 >= NNODE * HID / 4) return;
    int row  = t4 >> 5;          // 32 float4 per row
    int head = (t4 & 31) >> 2;   // 4 float4 per head
    float d = g_den[(size_t)row * 8 + head];
    float wn = (d > 0.0f) ? (1.0f / d) : 0.0f;
    float4 v = ((const float4*)g_attn)[t4];
    v.x *= wn; v.y *= wn; v.z *= wn; v.w *= wn;
    uint32_t h0, l0, h1, l1;
    split_pack(v.x, v.y, h0, l0);
    split_pack(v.z, v.w, h1, l1);
    *(uint2*)(hi + (size_t)t4 * 4) = make_uint2(h0, h1);
    *(uint2*)(lo + (size_t)t4 * 4) = make_uint2(l0, l1);
}

// ---------------- LayerNorm + modulate -> bf16 hi/lo ---------------------------
__global__ void ln_mod_kernel(const float* __restrict__ X,
                              int shift_off, int scale_off,
                              __nv_bfloat16* __restrict__ out_hi,
                              __nv_bfloat16* __restrict__ out_lo) {
    int warp = (blockIdx.x * blockDim.x + threadIdx.x) >> 5;
    if (warp >= NNODE) return;
    int lane = threadIdx.x & 31;
    const float4 v = *(const float4*)(X + (size_t)warp * HID + lane * 4);
    float s  = v.x + v.y + v.z + v.w;
    float sq = v.x * v.x + v.y * v.y + v.z * v.z + v.w * v.w;
    #pragma unroll
    for (int o = 16; o > 0; o >>= 1) {
        s  += __shfl_xor_sync(0xffffffffu, s,  o);
        sq += __shfl_xor_sync(0xffffffffu, sq, o);
    }
    float mean = s * (1.0f / HID);
    float var  = sq * (1.0f / HID) - mean * mean;
    float rstd = rsqrtf(var + 1e-6f);
    const float4 sh = *(const float4*)(g_mods + (size_t)warp * 768 + shift_off + lane * 4);
    const float4 sc = *(const float4*)(g_mods + (size_t)warp * 768 + scale_off + lane * 4);
    float4 o4;
    o4.x = (v.x - mean) * rstd * (1.0f + sc.x) + sh.x;
    o4.y = (v.y - mean) * rstd * (1.0f + sc.y) + sh.y;
    o4.z = (v.z - mean) * rstd * (1.0f + sc.z) + sh.z;
    o4.w = (v.w - mean) * rstd * (1.0f + sc.w) + sh.w;
    uint32_t h0, l0, h1, l1;
    split_pack(o4.x, o4.y, h0, l0);
    split_pack(o4.z, o4.w, h1, l1);
    *(uint2*)(out_hi + (size_t)warp * HID + lane * 4) = make_uint2(h0, h1);
    *(uint2*)(out_lo + (size_t)warp * HID + lane * 4) = make_uint2(l0, l1);
}

// ---------------- bf16x3 mma.sync GEMM, cp.async 2-stage pipeline --------------
// 128x128 tile, 256 thr, warp=32x64, KB=32 per chunk.
// A is pre-split bf16 hi/lo [M,K].  EPI: 0=none 1=gelu 2=res+gate*(acc+bias)
// 3=gelu->bf16 hi/lo.  Dynamic smem: 2 stages x (Ahi|Alo|Bhi|Blo) x 128x40 bf16.
#define SLDA 40
#define STAGE_B 40960      // 4 * 128 * 40 * 2
#define SM_TOT  81920
template<int EPI>
__global__ __launch_bounds__(256, 2)
void mma_gemm(const __nv_bfloat16* __restrict__ AHif,
              const __nv_bfloat16* __restrict__ ALof,
              const __nv_bfloat16* __restrict__ BThi,
              const __nv_bfloat16* __restrict__ BTlo,
              const float* __restrict__ bias,
              const float* __restrict__ gate,   // row stride 768 (EPI==2)
              const float* __restrict__ res,    // row stride N   (EPI==2)
              float* __restrict__ C,
              __nv_bfloat16* __restrict__ Chi,  // EPI==3
              __nv_bfloat16* __restrict__ Clo,  // EPI==3
              int M, int N, int K) {
    extern __shared__ char smem[];
    const uint32_t sbase = smem_u32(smem);

    const int tid  = threadIdx.x;
    const int lane = tid & 31;
    const int w    = tid >> 5;
    const int row0 = blockIdx.y * 128;
    const int col0 = blockIdx.x * 128;
    const int wr   = (w >> 1) * 32;
    const int wc   = (w & 1) * 64;

    float acc[2][8][4];
    #pragma unroll
    for (int i = 0; i < 2; i++)
        #pragma unroll
        for (int j = 0; j < 8; j++)
            #pragma unroll
            for (int q = 0; q < 4; q++) acc[i][j][q] = 0.0f;

    const int a_row_l = wr + (lane & 15);
    const int a_col_l = (lane >> 4) * 8;
    const int b_row_l = wc + ((lane >> 4) & 1) * 8 + (lane & 7);
    const int b_col_l = ((lane >> 3) & 1) * 8;

    // per-thread copy slots: idx = i*256+tid; r=idx>>2 (row), pc=idx&3 (16B piece)
    const int cp_r0 = tid >> 2, cp_p = (tid & 3);

    auto prefetch = [&](int ch) {
        const int k0 = ch * 32;
        const uint32_t so = sbase + (uint32_t)(ch & 1) * STAGE_B;
        #pragma unroll
        for (int i = 0; i < 2; i++) {
            int r = cp_r0 + i * 64;
            int gr = row0 + r;
            bool ok = gr < M;
            const size_t arow = (size_t)(ok ? gr : 0) * K + k0;
            uint32_t d = so + (uint32_t)(r * 80 + cp_p * 16);
            cpa16(d,         (const char*)(AHif + arow) + cp_p * 16, ok);
            cpa16(d + 10240, (const char*)(ALof + arow) + cp_p * 16, ok);
            const size_t brow = (size_t)(col0 + r) * K + k0;
            cpa16(d + 20480, (const char*)(BThi + brow) + cp_p * 16, true);
            cpa16(d + 30720, (const char*)(BTlo + brow) + cp_p * 16, true);
        }
        asm volatile("cp.async.commit_group;");
    };

    const int nchunk = K >> 5;
    prefetch(0);
    for (int ch = 0; ch < nchunk; ch++) {
        if (ch + 1 < nchunk) {
            prefetch(ch + 1);
            asm volatile("cp.async.wait_group 1;");
        } else {
            asm volatile("cp.async.wait_group 0;");
        }
        __syncthreads();

        const uint32_t so = sbase + (uint32_t)(ch & 1) * STAGE_B;
        #pragma unroll
        for (int ks = 0; ks < 2; ks++) {
            uint32_t ah[2][4], al[2][4];
            #pragma unroll
            for (int mt = 0; mt < 2; mt++) {
                uint32_t off = so + (uint32_t)(((a_row_l + mt * 16) * SLDA + a_col_l + ks * 16) * 2);
                ldsm4(ah[mt], off);
                ldsm4(al[mt], off + 10240);
            }
            #pragma unroll
            for (int np = 0; np < 4; np++) {
                uint32_t bh[4], bl[4];
                uint32_t off = so + 20480 + (uint32_t)(((b_row_l + np * 16) * SLDA + b_col_l + ks * 16) * 2);
                ldsm4(bh, off);
                ldsm4(bl, off + 10240);
                #pragma unroll
                for (int mt = 0; mt < 2; mt++) {
                    mma_bf16(acc[mt][np * 2],     ah[mt], bh[0], bh[1]);
                    mma_bf16(acc[mt][np * 2],     ah[mt], bl[0], bl[1]);
                    mma_bf16(acc[mt][np * 2],     al[mt], bh[0], bh[1]);
                    mma_bf16(acc[mt][np * 2 + 1], ah[mt], bh[2], bh[3]);
                    mma_bf16(acc[mt][np * 2 + 1], ah[mt], bl[2], bl[3]);
                    mma_bf16(acc[mt][np * 2 + 1], al[mt], bh[2], bh[3]);
                }
            }
        }
        __syncthreads();
    }

    // ---- epilogue: direct to global, fragment layout ----
    #pragma unroll
    for (int mt = 0; mt < 2; mt++) {
        #pragma unroll
        for (int nt = 0; nt < 8; nt++) {
            int gc = col0 + wc + nt * 8 + (lane & 3) * 2;
            #pragma unroll
            for (int g = 0; g < 2; g++) {
                int gr = row0 + wr + mt * 16 + (lane >> 2) + g * 8;
                if (gr < M) {
                    float vx = acc[mt][nt][g * 2];
                    float vy = acc[mt][nt][g * 2 + 1];
                    if (bias != nullptr) {
                        float2 b2 = *(const float2*)(bias + gc);
                        vx += b2.x; vy += b2.y;
                    }
                    if (EPI == 1 || EPI == 3) {
                        vx = gelu_tanh(vx); vy = gelu_tanh(vy);
                    } else if (EPI == 2) {
                        float2 g2 = *(const float2*)(gate + (size_t)gr * 768 + gc);
                        float2 r2 = *(const float2*)(res + (size_t)gr * N + gc);
                        vx = r2.x + g2.x * vx;
                        vy = r2.y + g2.y * vy;
                    }
                    if (EPI == 3) {
                        uint32_t hw, lw;
                        split_pack(vx, vy, hw, lw);
                        *(uint32_t*)(Chi + (size_t)gr * N + gc) = hw;
                        *(uint32_t*)(Clo + (size_t)gr * N + gc) = lw;
                    } else {
                        *(float2*)(C + (size_t)gr * N + gc) = make_float2(vx, vy);
                    }
                }
            }
        }
    }
}

// ---------------- single-pass edge attention -----------------------------------
__global__ void edge_attn_kernel() {
    int e = (blockIdx.x * blockDim.x + threadIdx.x) >> 5;
    if (e >= NEDGE) return;
    int lane = threadIdx.x & 31;
    int src = g_src[e];
    int dst = g_dst[e];
    const float4 q = *(const float4*)(g_qkv + (size_t)dst * 384 + lane * 4);
    const float4 k = *(const float4*)(g_qkv + (size_t)src * 384 + 128 + lane * 4);
    float p = q.x * k.x + q.y * k.y + q.z * k.z + q.w * k.w;
    p += __shfl_xor_sync(0xffffffffu, p, 1);
    p += __shfl_xor_sync(0xffffffffu, p, 2);
    float ex = __expf(p * 0.25f);
    const float4 v = *(const float4*)(g_qkv + (size_t)src * 384 + 256 + lane * 4);
    float* pd = g_attn + (size_t)dst * HID + lane * 4;
    asm volatile("red.global.add.v4.f32 [%0], {%1, %2, %3, %4};"
                 :: "l"(pd), "f"(v.x * ex), "f"(v.y * ex), "f"(v.z * ex), "f"(v.w * ex)
                 : "memory");
    if ((lane & 3) == 0)
        atomicAdd(&g_den[(size_t)dst * 8 + (lane >> 2)], ex);
}

// ---------------- launch -------------------------------------------------------
static inline int cdiv(int a, int b) { return (a + b - 1) / b; }

extern "C" void kernel_launch(void* const* d_in, const int* in_sizes, int n_in,
                              void* d_out, int out_size) {
    const float* x      = (const float*)d_in[0];
    const void*  ei     = d_in[1];
    const float* c      = (const float*)d_in[2];
    const float* w_qkv  = (const float*)d_in[3];
    const float* w_proj = (const float*)d_in[4];
    const float* b_proj = (const float*)d_in[5];
    const float* w_mlp1 = (const float*)d_in[6];
    const float* b_mlp1 = (const float*)d_in[7];
    const float* w_mlp2 = (const float*)d_in[8];
    const float* b_mlp2 = (const float*)d_in[9];
    const float* w_ada  = (const float*)d_in[10];
    const float* b_ada  = (const float*)d_in[11];
    float*       out    = (float*)d_out;

    float *mods, *qkv, *x1;
    __nv_bfloat16 *wthi, *wtlo, *xmh, *xml, *hh, *hl;
    cudaGetSymbolAddress((void**)&mods, g_mods);
    cudaGetSymbolAddress((void**)&qkv,  g_qkv);
    cudaGetSymbolAddress((void**)&x1,   g_x1);
    cudaGetSymbolAddress((void**)&wthi, g_wthi);
    cudaGetSymbolAddress((void**)&wtlo, g_wtlo);
    cudaGetSymbolAddress((void**)&xmh,  g_xmh);
    cudaGetSymbolAddress((void**)&xml,  g_xml);
    cudaGetSymbolAddress((void**)&hh,   g_hh);
    cudaGetSymbolAddress((void**)&hl,   g_hl);

    cudaFuncSetAttribute(mma_gemm<0>, cudaFuncAttributeMaxDynamicSharedMemorySize, SM_TOT);
    cudaFuncSetAttribute(mma_gemm<2>, cudaFuncAttributeMaxDynamicSharedMemorySize, SM_TOT);
    cudaFuncSetAttribute(mma_gemm<3>, cudaFuncAttributeMaxDynamicSharedMemorySize, SM_TOT);

    const int MB = cdiv(NNODE, 128);

    detect_kernel<<<1, 256>>>(ei);
    convert_init_kernel<<<cdiv(NNODE * HID, 256), 256>>>(ei);
    wsplit_all_kernel<<<cdiv(WTOT, 256), 256>>>(w_ada, w_qkv, w_proj, w_mlp1, w_mlp2);
    silu_split_kernel<<<cdiv(NNODE * HID / 4, 256), 256>>>(c, xmh, xml);

    // mods = silu(c) @ w_ada + b_ada            [N, 768]
    mma_gemm<0><<<dim3(768 / 128, MB), 256, SM_TOT>>>(
        xmh, xml, wthi + WOFF_ADA, wtlo + WOFF_ADA, b_ada,
        nullptr, nullptr, mods, nullptr, nullptr, NNODE, 768, HID);

    // xmod = modulate(LN(x), sh_msa, sc_msa) -> bf16 hi/lo
    ln_mod_kernel<<<cdiv(NNODE * 32, 256), 256>>>(x, 0, 128, xmh, xml);

    // qkv = xmod @ w_qkv                         [N, 384]
    mma_gemm<0><<<dim3(384 / 128, MB), 256, SM_TOT>>>(
        xmh, xml, wthi + WOFF_QKV, wtlo + WOFF_QKV, nullptr,
        nullptr, nullptr, qkv, nullptr, nullptr, NNODE, 384, HID);

    // graph attention: single pass (unnormalized aggregate + denominators)
    edge_attn_kernel<<<cdiv(NEDGE * 32, 256), 256>>>();

    // normalize + split attn
    attn_norm_split_kernel<<<cdiv(NNODE * HID / 4, 256), 256>>>(xmh, xml);

    // x1 = x + g_msa * ((attn/den) @ w_proj + b_proj)
    mma_gemm<2><<<dim3(1, MB), 256, SM_TOT>>>(
        xmh, xml, wthi + WOFF_PROJ, wtlo + WOFF_PROJ, b_proj,
        mods + 256, x, x1, nullptr, nullptr, NNODE, HID, HID);

    // hmod = modulate(LN(x1), sh_mlp, sc_mlp) -> bf16 hi/lo
    ln_mod_kernel<<<cdiv(NNODE * 32, 256), 256>>>(x1, 384, 512, xmh, xml);

    // h = gelu(hmod @ w_mlp1 + b_mlp1) -> bf16 hi/lo        [N, 512]
    mma_gemm<3><<<dim3(MLPD / 128, MB), 256, SM_TOT>>>(
        xmh, xml, wthi + WOFF_MLP1, wtlo + WOFF_MLP1, b_mlp1,
        nullptr, nullptr, nullptr, hh, hl, NNODE, MLPD, HID);

    // out = x1 + g_mlp * (h @ w_mlp2 + b_mlp2)
    mma_gemm<2><<<dim3(1, MB), 256, SM_TOT>>>(
        hh, hl, wthi + WOFF_MLP2, wtlo + WOFF_MLP2, b_mlp2,
        mods + 640, x1, out, nullptr, nullptr, NNODE, HID, MLPD);
}

// round 12
// speedup vs baseline: 1.2772x; 1.0715x over previous
#include <cuda_runtime.h>
#include <cuda_bf16.h>
#include <math_constants.h>
#include <cstdint>

#define HID  128
#define NNODE 50000
#define NEDGE 800000
#define MLPD 512

// ---------------- scratch (static device globals; no runtime alloc) ------------
__device__ __align__(16) float g_mods [(size_t)NNODE * 768];
__device__ __align__(16) float g_qkv  [(size_t)NNODE * 384];
__device__ __align__(16) float g_x1   [(size_t)NNODE * HID];
// pre-split activations (bf16 hi/lo) — reused sequentially
__device__ __align__(16) __nv_bfloat16 g_xmh[(size_t)NNODE * HID];
__device__ __align__(16) __nv_bfloat16 g_xml[(size_t)NNODE * HID];
__device__ __align__(16) __nv_bfloat16 g_hh [(size_t)NNODE * MLPD];
__device__ __align__(16) __nv_bfloat16 g_hl [(size_t)NNODE * MLPD];
// CSR (dst-major) edge structure
__device__ int g_src[NEDGE];
__device__ int g_dst[NEDGE];
__device__ int g_psrc[NEDGE];        // src ids grouped by dst
__device__ int g_cnt[NNODE];
__device__ int g_off[NNODE + 1];
__device__ int g_woff[NNODE];
__device__ int g_is32;

// transposed+split weights: WT[N][K] bf16, K contiguous
#define WOFF_ADA  0
#define WOFF_QKV  98304
#define WOFF_PROJ 147456
#define WOFF_MLP1 163840
#define WOFF_MLP2 229376
#define WTOT      294912
__device__ __align__(16) __nv_bfloat16 g_wthi[WTOT];
__device__ __align__(16) __nv_bfloat16 g_wtlo[WTOT];

// ---------------- helpers ------------------------------------------------------
__device__ __forceinline__ float siluf(float v) {
    return v / (1.0f + __expf(-v));
}
__device__ __forceinline__ float gelu_tanh(float v) {
    float v3 = v * v * v;
    float t = tanhf(0.7978845608028654f * (v + 0.044715f * v3));
    return 0.5f * v * (1.0f + t);
}
__device__ __forceinline__ uint32_t smem_u32(const void* p) {
    uint32_t a;
    asm("{ .reg .u64 t; cvta.to.shared.u64 t, %1; cvt.u32.u64 %0, t; }" : "=r"(a) : "l"(p));
    return a;
}
__device__ __forceinline__ void ldsm4(uint32_t* r, uint32_t addr) {
    asm volatile("ldmatrix.sync.aligned.m8n8.x4.shared.b16 {%0,%1,%2,%3}, [%4];"
                 : "=r"(r[0]), "=r"(r[1]), "=r"(r[2]), "=r"(r[3]) : "r"(addr));
}
__device__ __forceinline__ void mma_bf16(float* d, const uint32_t* a,
                                         uint32_t b0, uint32_t b1) {
    asm volatile(
        "mma.sync.aligned.m16n8k16.row.col.f32.bf16.bf16.f32 "
        "{%0,%1,%2,%3}, {%4,%5,%6,%7}, {%8,%9}, {%0,%1,%2,%3};"
        : "+f"(d[0]), "+f"(d[1]), "+f"(d[2]), "+f"(d[3])
        : "r"(a[0]), "r"(a[1]), "r"(a[2]), "r"(a[3]), "r"(b0), "r"(b1));
}
__device__ __forceinline__ void split_pack(float x, float y, uint32_t& hw, uint32_t& lw) {
    __nv_bfloat16 hx = __float2bfloat16(x);
    __nv_bfloat16 hy = __float2bfloat16(y);
    __nv_bfloat16 lx = __float2bfloat16(x - __bfloat162float(hx));
    __nv_bfloat16 ly = __float2bfloat16(y - __bfloat162float(hy));
    __nv_bfloat162 hp(hx, hy), lp(lx, ly);
    memcpy(&hw, &hp, 4);
    memcpy(&lw, &lp, 4);
}
__device__ __forceinline__ void cpa16(uint32_t dst, const void* src, bool valid) {
    int sz = valid ? 16 : 0;
    asm volatile("cp.async.cg.shared.global [%0], [%1], 16, %2;"
                 :: "r"(dst), "l"(src), "r"(sz));
}

// ---------------- edge-index dtype detection + cnt zero ------------------------
__global__ void detect_kernel(const void* ei_raw) {
    const long long* p = (const long long*)ei_raw;
    int bad = 0;
    for (int i = threadIdx.x; i < 256; i += blockDim.x) {
        long long v = p[i];
        if (v < 0 || v >= NNODE) bad = 1;
    }
    bad = __syncthreads_or(bad);
    if (threadIdx.x == 0) g_is32 = bad;
    for (int i = threadIdx.x; i < NNODE; i += blockDim.x) g_cnt[i] = 0;
}

// ---------------- convert + dst histogram --------------------------------------
__global__ void convert_kernel(const void* ei_raw) {
    int e = blockIdx.x * blockDim.x + threadIdx.x;
    if (e >= NEDGE) return;
    int s, d;
    if (g_is32) {
        const int* p = (const int*)ei_raw;
        s = p[e]; d = p[NEDGE + e];
    } else {
        const long long* p = (const long long*)ei_raw;
        s = (int)p[e]; d = (int)p[NEDGE + e];
    }
    g_src[e] = s;
    g_dst[e] = d;
    atomicAdd(&g_cnt[d], 1);
}

// ---------------- single-block exclusive scan over g_cnt -----------------------
__global__ void scan_kernel() {
    const int tid  = threadIdx.x;
    const int lane = tid & 31, wid = tid >> 5;
    __shared__ int wsum[32];
    __shared__ int s_carry;
    if (tid == 0) s_carry = 0;
    __syncthreads();
    for (int base = 0; base < NNODE; base += 1024) {
        int i = base + tid;
        int v = (i < NNODE) ? g_cnt[i] : 0;
        int x = v;
        #pragma unroll
        for (int o = 1; o < 32; o <<= 1) {
            int t = __shfl_up_sync(0xffffffffu, x, o);
            if (lane >= o) x += t;
        }
        if (lane == 31) wsum[wid] = x;
        __syncthreads();
        if (wid == 0) {
            int y = wsum[lane];
            #pragma unroll
            for (int o = 1; o < 32; o <<= 1) {
                int t = __shfl_up_sync(0xffffffffu, y, o);
                if (lane >= o) y += t;
            }
            wsum[lane] = y;
        }
        __syncthreads();
        int warp_excl = (wid == 0) ? 0 : wsum[wid - 1];
        int incl = x + warp_excl;
        int carry = s_carry;
        if (i < NNODE) {
            g_off[i]  = carry + incl - v;
            g_woff[i] = carry + incl - v;
        }
        __syncthreads();
        if (tid == 1023) s_carry = carry + incl;
        __syncthreads();
    }
    if (tid == 0) g_off[NNODE] = s_carry;
}

// ---------------- scatter src ids into dst-major order -------------------------
__global__ void scatter_kernel() {
    int e = blockIdx.x * blockDim.x + threadIdx.x;
    if (e >= NEDGE) return;
    int pos = atomicAdd(&g_woff[g_dst[e]], 1);
    g_psrc[pos] = g_src[e];
}

// ---------------- ALL weight transposes + bf16 splits in one kernel ------------
__global__ void wsplit_all_kernel(const float* __restrict__ w_ada,
                                  const float* __restrict__ w_qkv,
                                  const float* __restrict__ w_proj,
                                  const float* __restrict__ w_mlp1,
                                  const float* __restrict__ w_mlp2) {
    int t = blockIdx.x * blockDim.x + threadIdx.x;
    if (t >= WTOT) return;
    const float* W;
    int Kg, Ng, l;
    if (t < WOFF_QKV)       { W = w_ada;  Kg = 128; Ng = 768; l = t - WOFF_ADA; }
    else if (t < WOFF_PROJ) { W = w_qkv;  Kg = 128; Ng = 384; l = t - WOFF_QKV; }
    else if (t < WOFF_MLP1) { W = w_proj; Kg = 128; Ng = 128; l = t - WOFF_PROJ; }
    else if (t < WOFF_MLP2) { W = w_mlp1; Kg = 128; Ng = 512; l = t - WOFF_MLP1; }
    else                    { W = w_mlp2; Kg = 512; Ng = 128; l = t - WOFF_MLP2; }
    int n = l / Kg, k = l % Kg;
    float v = W[(size_t)k * Ng + n];
    __nv_bfloat16 h = __float2bfloat16(v);
    g_wthi[t] = h;
    g_wtlo[t] = __float2bfloat16(v - __bfloat162float(h));
}

// ---------------- silu(c) -> bf16 hi/lo ----------------------------------------
__global__ void silu_split_kernel(const float* __restrict__ c,
                                  __nv_bfloat16* __restrict__ hi,
                                  __nv_bfloat16* __restrict__ lo) {
    int t4 = blockIdx.x * blockDim.x + threadIdx.x;
    if (t4 >= NNODE * HID / 4) return;
    float4 v = ((const float4*)c)[t4];
    v.x = siluf(v.x); v.y = siluf(v.y); v.z = siluf(v.z); v.w = siluf(v.w);
    uint32_t h0, l0, h1, l1;
    split_pack(v.x, v.y, h0, l0);
    split_pack(v.z, v.w, h1, l1);
    *(uint2*)(hi + (size_t)t4 * 4) = make_uint2(h0, h1);
    *(uint2*)(lo + (size_t)t4 * 4) = make_uint2(l0, l1);
}

// ---------------- LayerNorm + modulate -> bf16 hi/lo ---------------------------
__global__ void ln_mod_kernel(const float* __restrict__ X,
                              int shift_off, int scale_off,
                              __nv_bfloat16* __restrict__ out_hi,
                              __nv_bfloat16* __restrict__ out_lo) {
    int warp = (blockIdx.x * blockDim.x + threadIdx.x) >> 5;
    if (warp >= NNODE) return;
    int lane = threadIdx.x & 31;
    const float4 v = *(const float4*)(X + (size_t)warp * HID + lane * 4);
    float s  = v.x + v.y + v.z + v.w;
    float sq = v.x * v.x + v.y * v.y + v.z * v.z + v.w * v.w;
    #pragma unroll
    for (int o = 16; o > 0; o >>= 1) {
        s  += __shfl_xor_sync(0xffffffffu, s,  o);
        sq += __shfl_xor_sync(0xffffffffu, sq, o);
    }
    float mean = s * (1.0f / HID);
    float var  = sq * (1.0f / HID) - mean * mean;
    float rstd = rsqrtf(var + 1e-6f);
    const float4 sh = *(const float4*)(g_mods + (size_t)warp * 768 + shift_off + lane * 4);
    const float4 sc = *(const float4*)(g_mods + (size_t)warp * 768 + scale_off + lane * 4);
    float4 o4;
    o4.x = (v.x - mean) * rstd * (1.0f + sc.x) + sh.x;
    o4.y = (v.y - mean) * rstd * (1.0f + sc.y) + sh.y;
    o4.z = (v.z - mean) * rstd * (1.0f + sc.z) + sh.z;
    o4.w = (v.w - mean) * rstd * (1.0f + sc.w) + sh.w;
    uint32_t h0, l0, h1, l1;
    split_pack(o4.x, o4.y, h0, l0);
    split_pack(o4.z, o4.w, h1, l1);
    *(uint2*)(out_hi + (size_t)warp * HID + lane * 4) = make_uint2(h0, h1);
    *(uint2*)(out_lo + (size_t)warp * HID + lane * 4) = make_uint2(l0, l1);
}

// ---------------- dst-major attention: one warp per destination node -----------
// q loaded once; edges iterated from CSR; register accumulation; normalized
// output written once as pre-split bf16 hi/lo (feeds proj GEMM directly).
__global__ void dst_attn_kernel(__nv_bfloat16* __restrict__ hi,
                                __nv_bfloat16* __restrict__ lo) {
    int d = (blockIdx.x * blockDim.x + threadIdx.x) >> 5;
    if (d >= NNODE) return;
    int lane = threadIdx.x & 31;
    const float4 q = *(const float4*)(g_qkv + (size_t)d * 384 + lane * 4);
    float4 acc = make_float4(0.f, 0.f, 0.f, 0.f);
    float den = 0.0f;
    const int b = g_off[d], e = g_off[d + 1];
    for (int i = b; i < e; i++) {
        int src = g_psrc[i];
        const float4 k = *(const float4*)(g_qkv + (size_t)src * 384 + 128 + lane * 4);
        const float4 v = *(const float4*)(g_qkv + (size_t)src * 384 + 256 + lane * 4);
        float p = q.x * k.x + q.y * k.y + q.z * k.z + q.w * k.w;
        p += __shfl_xor_sync(0xffffffffu, p, 1);
        p += __shfl_xor_sync(0xffffffffu, p, 2);
        float ex = __expf(p * 0.25f);
        acc.x += ex * v.x; acc.y += ex * v.y;
        acc.z += ex * v.z; acc.w += ex * v.w;
        den += ex;
    }
    float wn = (den > 0.0f) ? (1.0f / den) : 0.0f;
    acc.x *= wn; acc.y *= wn; acc.z *= wn; acc.w *= wn;
    uint32_t h0, l0, h1, l1;
    split_pack(acc.x, acc.y, h0, l0);
    split_pack(acc.z, acc.w, h1, l1);
    *(uint2*)(hi + (size_t)d * HID + lane * 4) = make_uint2(h0, h1);
    *(uint2*)(lo + (size_t)d * HID + lane * 4) = make_uint2(l0, l1);
}

// ---------------- bf16x3 mma.sync GEMM, cp.async 2-stage pipeline --------------
#define SLDA 40
#define STAGE_B 40960      // 4 * 128 * 40 * 2
#define SM_TOT  81920
template<int EPI>   // 0=none 2=res+gate*(acc+bias) 3=gelu->bf16 hi/lo
__global__ __launch_bounds__(256, 2)
void mma_gemm(const __nv_bfloat16* __restrict__ AHif,
              const __nv_bfloat16* __restrict__ ALof,
              const __nv_bfloat16* __restrict__ BThi,
              const __nv_bfloat16* __restrict__ BTlo,
              const float* __restrict__ bias,
              const float* __restrict__ gate,   // row stride 768 (EPI==2)
              const float* __restrict__ res,    // row stride N   (EPI==2)
              float* __restrict__ C,
              __nv_bfloat16* __restrict__ Chi,  // EPI==3
              __nv_bfloat16* __restrict__ Clo,  // EPI==3
              int M, int N, int K) {
    extern __shared__ char smem[];
    const uint32_t sbase = smem_u32(smem);

    const int tid  = threadIdx.x;
    const int lane = tid & 31;
    const int w    = tid >> 5;
    const int row0 = blockIdx.y * 128;
    const int col0 = blockIdx.x * 128;
    const int wr   = (w >> 1) * 32;
    const int wc   = (w & 1) * 64;

    float acc[2][8][4];
    #pragma unroll
    for (int i = 0; i < 2; i++)
        #pragma unroll
        for (int j = 0; j < 8; j++)
            #pragma unroll
            for (int q = 0; q < 4; q++) acc[i][j][q] = 0.0f;

    const int a_row_l = wr + (lane & 15);
    const int a_col_l = (lane >> 4) * 8;
    const int b_row_l = wc + ((lane >> 4) & 1) * 8 + (lane & 7);
    const int b_col_l = ((lane >> 3) & 1) * 8;

    const int cp_r0 = tid >> 2, cp_p = (tid & 3);

    auto prefetch = [&](int ch) {
        const int k0 = ch * 32;
        const uint32_t so = sbase + (uint32_t)(ch & 1) * STAGE_B;
        #pragma unroll
        for (int i = 0; i < 2; i++) {
            int r = cp_r0 + i * 64;
            int gr = row0 + r;
            bool ok = gr < M;
            const size_t arow = (size_t)(ok ? gr : 0) * K + k0;
            uint32_t d = so + (uint32_t)(r * 80 + cp_p * 16);
            cpa16(d,         (const char*)(AHif + arow) + cp_p * 16, ok);
            cpa16(d + 10240, (const char*)(ALof + arow) + cp_p * 16, ok);
            const size_t brow = (size_t)(col0 + r) * K + k0;
            cpa16(d + 20480, (const char*)(BThi + brow) + cp_p * 16, true);
            cpa16(d + 30720, (const char*)(BTlo + brow) + cp_p * 16, true);
        }
        asm volatile("cp.async.commit_group;");
    };

    const int nchunk = K >> 5;
    prefetch(0);
    for (int ch = 0; ch < nchunk; ch++) {
        if (ch + 1 < nchunk) {
            prefetch(ch + 1);
            asm volatile("cp.async.wait_group 1;");
        } else {
            asm volatile("cp.async.wait_group 0;");
        }
        __syncthreads();

        const uint32_t so = sbase + (uint32_t)(ch & 1) * STAGE_B;
        #pragma unroll
        for (int ks = 0; ks < 2; ks++) {
            uint32_t ah[2][4], al[2][4];
            #pragma unroll
            for (int mt = 0; mt < 2; mt++) {
                uint32_t off = so + (uint32_t)(((a_row_l + mt * 16) * SLDA + a_col_l + ks * 16) * 2);
                ldsm4(ah[mt], off);
                ldsm4(al[mt], off + 10240);
            }
            #pragma unroll
            for (int np = 0; np < 4; np++) {
                uint32_t bh[4], bl[4];
                uint32_t off = so + 20480 + (uint32_t)(((b_row_l + np * 16) * SLDA + b_col_l + ks * 16) * 2);
                ldsm4(bh, off);
                ldsm4(bl, off + 10240);
                #pragma unroll
                for (int mt = 0; mt < 2; mt++) {
                    mma_bf16(acc[mt][np * 2],     ah[mt], bh[0], bh[1]);
                    mma_bf16(acc[mt][np * 2],     ah[mt], bl[0], bl[1]);
                    mma_bf16(acc[mt][np * 2],     al[mt], bh[0], bh[1]);
                    mma_bf16(acc[mt][np * 2 + 1], ah[mt], bh[2], bh[3]);
                    mma_bf16(acc[mt][np * 2 + 1], ah[mt], bl[2], bl[3]);
                    mma_bf16(acc[mt][np * 2 + 1], al[mt], bh[2], bh[3]);
                }
            }
        }
        __syncthreads();
    }

    // ---- epilogue ----
    #pragma unroll
    for (int mt = 0; mt < 2; mt++) {
        #pragma unroll
        for (int nt = 0; nt < 8; nt++) {
            int gc = col0 + wc + nt * 8 + (lane & 3) * 2;
            #pragma unroll
            for (int g = 0; g < 2; g++) {
                int gr = row0 + wr + mt * 16 + (lane >> 2) + g * 8;
                if (gr < M) {
                    float vx = acc[mt][nt][g * 2];
                    float vy = acc[mt][nt][g * 2 + 1];
                    if (bias != nullptr) {
                        float2 b2 = *(const float2*)(bias + gc);
                        vx += b2.x; vy += b2.y;
                    }
                    if (EPI == 3) {
                        vx = gelu_tanh(vx); vy = gelu_tanh(vy);
                    } else if (EPI == 2) {
                        float2 g2 = *(const float2*)(gate + (size_t)gr * 768 + gc);
                        float2 r2 = *(const float2*)(res + (size_t)gr * N + gc);
                        vx = r2.x + g2.x * vx;
                        vy = r2.y + g2.y * vy;
                    }
                    if (EPI == 3) {
                        uint32_t hw, lw;
                        split_pack(vx, vy, hw, lw);
                        *(uint32_t*)(Chi + (size_t)gr * N + gc) = hw;
                        *(uint32_t*)(Clo + (size_t)gr * N + gc) = lw;
                    } else {
                        *(float2*)(C + (size_t)gr * N + gc) = make_float2(vx, vy);
                    }
                }
            }
        }
    }
}

// ---------------- launch -------------------------------------------------------
static inline int cdiv(int a, int b) { return (a + b - 1) / b; }

extern "C" void kernel_launch(void* const* d_in, const int* in_sizes, int n_in,
                              void* d_out, int out_size) {
    const float* x      = (const float*)d_in[0];
    const void*  ei     = d_in[1];
    const float* c      = (const float*)d_in[2];
    const float* w_qkv  = (const float*)d_in[3];
    const float* w_proj = (const float*)d_in[4];
    const float* b_proj = (const float*)d_in[5];
    const float* w_mlp1 = (const float*)d_in[6];
    const float* b_mlp1 = (const float*)d_in[7];
    const float* w_mlp2 = (const float*)d_in[8];
    const float* b_mlp2 = (const float*)d_in[9];
    const float* w_ada  = (const float*)d_in[10];
    const float* b_ada  = (const float*)d_in[11];
    float*       out    = (float*)d_out;

    float *mods, *qkv, *x1;
    __nv_bfloat16 *wthi, *wtlo, *xmh, *xml, *hh, *hl;
    cudaGetSymbolAddress((void**)&mods, g_mods);
    cudaGetSymbolAddress((void**)&qkv,  g_qkv);
    cudaGetSymbolAddress((void**)&x1,   g_x1);
    cudaGetSymbolAddress((void**)&wthi, g_wthi);
    cudaGetSymbolAddress((void**)&wtlo, g_wtlo);
    cudaGetSymbolAddress((void**)&xmh,  g_xmh);
    cudaGetSymbolAddress((void**)&xml,  g_xml);
    cudaGetSymbolAddress((void**)&hh,   g_hh);
    cudaGetSymbolAddress((void**)&hl,   g_hl);

    cudaFuncSetAttribute(mma_gemm<0>, cudaFuncAttributeMaxDynamicSharedMemorySize, SM_TOT);
    cudaFuncSetAttribute(mma_gemm<2>, cudaFuncAttributeMaxDynamicSharedMemorySize, SM_TOT);
    cudaFuncSetAttribute(mma_gemm<3>, cudaFuncAttributeMaxDynamicSharedMemorySize, SM_TOT);

    const int MB = cdiv(NNODE, 128);

    detect_kernel<<<1, 256>>>(ei);                                                      // 0
    wsplit_all_kernel<<<cdiv(WTOT, 256), 256>>>(w_ada, w_qkv, w_proj, w_mlp1, w_mlp2);  // 1
    silu_split_kernel<<<cdiv(NNODE * HID / 4, 256), 256>>>(c, xmh, xml);                // 2

    // mods = silu(c) @ w_ada + b_ada            [N, 768]    (launch idx 3: ncu slot)
    mma_gemm<0><<<dim3(768 / 128, MB), 256, SM_TOT>>>(
        xmh, xml, wthi + WOFF_ADA, wtlo + WOFF_ADA, b_ada,
        nullptr, nullptr, mods, nullptr, nullptr, NNODE, 768, HID);

    // CSR build (independent of GEMM stream order, but serialized in-stream)
    convert_kernel<<<cdiv(NEDGE, 256), 256>>>(ei);
    scan_kernel<<<1, 1024>>>();
    scatter_kernel<<<cdiv(NEDGE, 256), 256>>>();

    // xmod = modulate(LN(x), sh_msa, sc_msa) -> bf16 hi/lo
    ln_mod_kernel<<<cdiv(NNODE * 32, 256), 256>>>(x, 0, 128, xmh, xml);

    // qkv = xmod @ w_qkv                         [N, 384]
    mma_gemm<0><<<dim3(384 / 128, MB), 256, SM_TOT>>>(
        xmh, xml, wthi + WOFF_QKV, wtlo + WOFF_QKV, nullptr,
        nullptr, nullptr, qkv, nullptr, nullptr, NNODE, 384, HID);

    // dst-major attention: writes normalized result pre-split into xmh/xml
    dst_attn_kernel<<<cdiv(NNODE * 32, 256), 256>>>(xmh, xml);

    // x1 = x + g_msa * (attn @ w_proj + b_proj)
    mma_gemm<2><<<dim3(1, MB), 256, SM_TOT>>>(
        xmh, xml, wthi + WOFF_PROJ, wtlo + WOFF_PROJ, b_proj,
        mods + 256, x, x1, nullptr, nullptr, NNODE, HID, HID);

    // hmod = modulate(LN(x1), sh_mlp, sc_mlp) -> bf16 hi/lo
    ln_mod_kernel<<<cdiv(NNODE * 32, 256), 256>>>(x1, 384, 512, xmh, xml);

    // h = gelu(hmod @ w_mlp1 + b_mlp1) -> bf16 hi/lo        [N, 512]
    mma_gemm<3><<<dim3(MLPD / 128, MB), 256, SM_TOT>>>(
        xmh, xml, wthi + WOFF_MLP1, wtlo + WOFF_MLP1, b_mlp1,
        nullptr, nullptr, nullptr, hh, hl, NNODE, MLPD, HID);

    // out = x1 + g_mlp * (h @ w_mlp2 + b_mlp2)
    mma_gemm<2><<<dim3(1, MB), 256, SM_TOT>>>(
        hh, hl, wthi + WOFF_MLP2, wtlo + WOFF_MLP2, b_mlp2,
        mods + 640, x1, out, nullptr, nullptr, NNODE, HID, MLPD);
}

// round 13
// speedup vs baseline: 1.5261x; 1.1949x over previous
#include <cuda_runtime.h>
#include <cuda_bf16.h>
#include <cuda_fp16.h>
#include <math_constants.h>
#include <cstdint>

#define HID  128
#define NNODE 50000
#define NEDGE 800000
#define MLPD 512

// ---------------- scratch (static device globals; no runtime alloc) ------------
__device__ __align__(16) float g_mods [(size_t)NNODE * 768];
__device__ __align__(16) float g_qkv  [(size_t)NNODE * 384];
__device__ __align__(16) float g_x1   [(size_t)NNODE * HID];
// fp16 activations (single precision-level; weights carry the compensation)
__device__ __align__(16) __half g_xa[(size_t)NNODE * HID];
__device__ __align__(16) __half g_ha[(size_t)NNODE * MLPD];
// CSR (dst-major) edge structure
__device__ int g_src[NEDGE];
__device__ int g_dst[NEDGE];
__device__ int g_psrc[NEDGE];
__device__ int g_cnt[NNODE];
__device__ int g_off[NNODE + 1];
__device__ int g_woff[NNODE];
__device__ int g_is32;

// transposed+split weights: WT[N][K] fp16 hi/lo, K contiguous
#define WOFF_ADA  0
#define WOFF_QKV  98304
#define WOFF_PROJ 147456
#define WOFF_MLP1 163840
#define WOFF_MLP2 229376
#define WTOT      294912
__device__ __align__(16) __half g_wthi[WTOT];
__device__ __align__(16) __half g_wtlo[WTOT];

// ---------------- helpers ------------------------------------------------------
__device__ __forceinline__ float siluf(float v) {
    return v / (1.0f + __expf(-v));
}
__device__ __forceinline__ float gelu_tanh(float v) {
    float v3 = v * v * v;
    float t = tanhf(0.7978845608028654f * (v + 0.044715f * v3));
    return 0.5f * v * (1.0f + t);
}
__device__ __forceinline__ uint32_t smem_u32(const void* p) {
    uint32_t a;
    asm("{ .reg .u64 t; cvta.to.shared.u64 t, %1; cvt.u32.u64 %0, t; }" : "=r"(a) : "l"(p));
    return a;
}
__device__ __forceinline__ void ldsm4(uint32_t* r, uint32_t addr) {
    asm volatile("ldmatrix.sync.aligned.m8n8.x4.shared.b16 {%0,%1,%2,%3}, [%4];"
                 : "=r"(r[0]), "=r"(r[1]), "=r"(r[2]), "=r"(r[3]) : "r"(addr));
}
__device__ __forceinline__ void mma_fp16(float* d, const uint32_t* a,
                                         uint32_t b0, uint32_t b1) {
    asm volatile(
        "mma.sync.aligned.m16n8k16.row.col.f32.f16.f16.f32 "
        "{%0,%1,%2,%3}, {%4,%5,%6,%7}, {%8,%9}, {%0,%1,%2,%3};"
        : "+f"(d[0]), "+f"(d[1]), "+f"(d[2]), "+f"(d[3])
        : "r"(a[0]), "r"(a[1]), "r"(a[2]), "r"(a[3]), "r"(b0), "r"(b1));
}
__device__ __forceinline__ uint32_t pack_h2(float x, float y) {
    __half2 h = __floats2half2_rn(x, y);
    uint32_t r;
    memcpy(&r, &h, 4);
    return r;
}
__device__ __forceinline__ void cpa16(uint32_t dst, const void* src, bool valid) {
    int sz = valid ? 16 : 0;
    asm volatile("cp.async.cg.shared.global [%0], [%1], 16, %2;"
                 :: "r"(dst), "l"(src), "r"(sz));
}

// ---------------- edge-index dtype detection + cnt zero ------------------------
__global__ void detect_kernel(const void* ei_raw) {
    const long long* p = (const long long*)ei_raw;
    int bad = 0;
    for (int i = threadIdx.x; i < 256; i += blockDim.x) {
        long long v = p[i];
        if (v < 0 || v >= NNODE) bad = 1;
    }
    bad = __syncthreads_or(bad);
    if (threadIdx.x == 0) g_is32 = bad;
    for (int i = threadIdx.x; i < NNODE; i += blockDim.x) g_cnt[i] = 0;
}

// ---------------- convert + dst histogram --------------------------------------
__global__ void convert_kernel(const void* ei_raw) {
    int e = blockIdx.x * blockDim.x + threadIdx.x;
    if (e >= NEDGE) return;
    int s, d;
    if (g_is32) {
        const int* p = (const int*)ei_raw;
        s = p[e]; d = p[NEDGE + e];
    } else {
        const long long* p = (const long long*)ei_raw;
        s = (int)p[e]; d = (int)p[NEDGE + e];
    }
    g_src[e] = s;
    g_dst[e] = d;
    atomicAdd(&g_cnt[d], 1);
}

// ---------------- single-block exclusive scan over g_cnt -----------------------
__global__ void scan_kernel() {
    const int tid  = threadIdx.x;
    const int lane = tid & 31, wid = tid >> 5;
    __shared__ int wsum[32];
    __shared__ int s_carry;
    if (tid == 0) s_carry = 0;
    __syncthreads();
    for (int base = 0; base < NNODE; base += 1024) {
        int i = base + tid;
        int v = (i < NNODE) ? g_cnt[i] : 0;
        int x = v;
        #pragma unroll
        for (int o = 1; o < 32; o <<= 1) {
            int t = __shfl_up_sync(0xffffffffu, x, o);
            if (lane >= o) x += t;
        }
        if (lane == 31) wsum[wid] = x;
        __syncthreads();
        if (wid == 0) {
            int y = wsum[lane];
            #pragma unroll
            for (int o = 1; o < 32; o <<= 1) {
                int t = __shfl_up_sync(0xffffffffu, y, o);
                if (lane >= o) y += t;
            }
            wsum[lane] = y;
        }
        __syncthreads();
        int warp_excl = (wid == 0) ? 0 : wsum[wid - 1];
        int incl = x + warp_excl;
        int carry = s_carry;
        if (i < NNODE) {
            g_off[i]  = carry + incl - v;
            g_woff[i] = carry + incl - v;
        }
        __syncthreads();
        if (tid == 1023) s_carry = carry + incl;
        __syncthreads();
    }
    if (tid == 0) g_off[NNODE] = s_carry;
}

// ---------------- scatter src ids into dst-major order -------------------------
__global__ void scatter_kernel() {
    int e = blockIdx.x * blockDim.x + threadIdx.x;
    if (e >= NEDGE) return;
    int pos = atomicAdd(&g_woff[g_dst[e]], 1);
    g_psrc[pos] = g_src[e];
}

// ---------------- ALL weight transposes + fp16 splits in one kernel ------------
__global__ void wsplit_all_kernel(const float* __restrict__ w_ada,
                                  const float* __restrict__ w_qkv,
                                  const float* __restrict__ w_proj,
                                  const float* __restrict__ w_mlp1,
                                  const float* __restrict__ w_mlp2) {
    int t = blockIdx.x * blockDim.x + threadIdx.x;
    if (t >= WTOT) return;
    const float* W;
    int Kg, Ng, l;
    if (t < WOFF_QKV)       { W = w_ada;  Kg = 128; Ng = 768; l = t - WOFF_ADA; }
    else if (t < WOFF_PROJ) { W = w_qkv;  Kg = 128; Ng = 384; l = t - WOFF_QKV; }
    else if (t < WOFF_MLP1) { W = w_proj; Kg = 128; Ng = 128; l = t - WOFF_PROJ; }
    else if (t < WOFF_MLP2) { W = w_mlp1; Kg = 128; Ng = 512; l = t - WOFF_MLP1; }
    else                    { W = w_mlp2; Kg = 512; Ng = 128; l = t - WOFF_MLP2; }
    int n = l / Kg, k = l % Kg;
    float v = W[(size_t)k * Ng + n];
    __half h = __float2half_rn(v);
    g_wthi[t] = h;
    g_wtlo[t] = __float2half_rn(v - __half2float(h));
}

// ---------------- silu(c) -> fp16 ----------------------------------------------
__global__ void silu_h_kernel(const float* __restrict__ c,
                              __half* __restrict__ o) {
    int t4 = blockIdx.x * blockDim.x + threadIdx.x;
    if (t4 >= NNODE * HID / 4) return;
    float4 v = ((const float4*)c)[t4];
    uint32_t a = pack_h2(siluf(v.x), siluf(v.y));
    uint32_t b = pack_h2(siluf(v.z), siluf(v.w));
    *(uint2*)(o + (size_t)t4 * 4) = make_uint2(a, b);
}

// ---------------- LayerNorm + modulate -> fp16 ---------------------------------
__global__ void ln_mod_kernel(const float* __restrict__ X,
                              int shift_off, int scale_off,
                              __half* __restrict__ o) {
    int warp = (blockIdx.x * blockDim.x + threadIdx.x) >> 5;
    if (warp >= NNODE) return;
    int lane = threadIdx.x & 31;
    const float4 v = *(const float4*)(X + (size_t)warp * HID + lane * 4);
    float s  = v.x + v.y + v.z + v.w;
    float sq = v.x * v.x + v.y * v.y + v.z * v.z + v.w * v.w;
    #pragma unroll
    for (int oo = 16; oo > 0; oo >>= 1) {
        s  += __shfl_xor_sync(0xffffffffu, s,  oo);
        sq += __shfl_xor_sync(0xffffffffu, sq, oo);
    }
    float mean = s * (1.0f / HID);
    float var  = sq * (1.0f / HID) - mean * mean;
    float rstd = rsqrtf(var + 1e-6f);
    const float4 sh = *(const float4*)(g_mods + (size_t)warp * 768 + shift_off + lane * 4);
    const float4 sc = *(const float4*)(g_mods + (size_t)warp * 768 + scale_off + lane * 4);
    float ox = (v.x - mean) * rstd * (1.0f + sc.x) + sh.x;
    float oy = (v.y - mean) * rstd * (1.0f + sc.y) + sh.y;
    float oz = (v.z - mean) * rstd * (1.0f + sc.z) + sh.z;
    float ow = (v.w - mean) * rstd * (1.0f + sc.w) + sh.w;
    *(uint2*)(o + (size_t)warp * HID + lane * 4) =
        make_uint2(pack_h2(ox, oy), pack_h2(oz, ow));
}

// ---------------- dst-major attention -> fp16 ----------------------------------
__global__ void dst_attn_kernel(__half* __restrict__ o) {
    int d = (blockIdx.x * blockDim.x + threadIdx.x) >> 5;
    if (d >= NNODE) return;
    int lane = threadIdx.x & 31;
    const float4 q = *(const float4*)(g_qkv + (size_t)d * 384 + lane * 4);
    float4 acc = make_float4(0.f, 0.f, 0.f, 0.f);
    float den = 0.0f;
    const int b = g_off[d], e = g_off[d + 1];
    for (int i = b; i < e; i++) {
        int src = g_psrc[i];
        const float4 k = *(const float4*)(g_qkv + (size_t)src * 384 + 128 + lane * 4);
        const float4 v = *(const float4*)(g_qkv + (size_t)src * 384 + 256 + lane * 4);
        float p = q.x * k.x + q.y * k.y + q.z * k.z + q.w * k.w;
        p += __shfl_xor_sync(0xffffffffu, p, 1);
        p += __shfl_xor_sync(0xffffffffu, p, 2);
        float ex = __expf(p * 0.25f);
        acc.x += ex * v.x; acc.y += ex * v.y;
        acc.z += ex * v.z; acc.w += ex * v.w;
        den += ex;
    }
    float wn = (den > 0.0f) ? (1.0f / den) : 0.0f;
    *(uint2*)(o + (size_t)d * HID + lane * 4) =
        make_uint2(pack_h2(acc.x * wn, acc.y * wn), pack_h2(acc.z * wn, acc.w * wn));
}

// ---------------- fp16x2 mma.sync GEMM, cp.async 2-stage pipeline --------------
// A single fp16 [M,K]; B split hi/lo fp16 [N,K].  D = A·Bhi + A·Blo.
// EPI: 0=none 2=res+gate*(acc+bias) 3=gelu->fp16 (Ch)
#define SLDA 40
#define STAGE_B 30720      // 3 * 128 * 40 * 2
#define SM_TOT  61440
template<int EPI>
__global__ __launch_bounds__(256, 2)
void mma_gemm(const __half* __restrict__ Af,
              const __half* __restrict__ BThi,
              const __half* __restrict__ BTlo,
              const float* __restrict__ bias,
              const float* __restrict__ gate,   // row stride 768 (EPI==2)
              const float* __restrict__ res,    // row stride N   (EPI==2)
              float* __restrict__ C,
              __half* __restrict__ Ch,          // EPI==3
              int M, int N, int K) {
    extern __shared__ char smem[];
    const uint32_t sbase = smem_u32(smem);

    const int tid  = threadIdx.x;
    const int lane = tid & 31;
    const int w    = tid >> 5;
    const int row0 = blockIdx.y * 128;
    const int col0 = blockIdx.x * 128;
    const int wr   = (w >> 1) * 32;
    const int wc   = (w & 1) * 64;

    float acc[2][8][4];
    #pragma unroll
    for (int i = 0; i < 2; i++)
        #pragma unroll
        for (int j = 0; j < 8; j++)
            #pragma unroll
            for (int q = 0; q < 4; q++) acc[i][j][q] = 0.0f;

    const int a_row_l = wr + (lane & 15);
    const int a_col_l = (lane >> 4) * 8;
    const int b_row_l = wc + ((lane >> 4) & 1) * 8 + (lane & 7);
    const int b_col_l = ((lane >> 3) & 1) * 8;

    const int cp_r0 = tid >> 2, cp_p = (tid & 3);

    auto prefetch = [&](int ch) {
        const int k0 = ch * 32;
        const uint32_t so = sbase + (uint32_t)(ch & 1) * STAGE_B;
        #pragma unroll
        for (int i = 0; i < 2; i++) {
            int r = cp_r0 + i * 64;
            int gr = row0 + r;
            bool ok = gr < M;
            const size_t arow = (size_t)(ok ? gr : 0) * K + k0;
            uint32_t d = so + (uint32_t)(r * 80 + cp_p * 16);
            cpa16(d, (const char*)(Af + arow) + cp_p * 16, ok);
            const size_t brow = (size_t)(col0 + r) * K + k0;
            cpa16(d + 10240, (const char*)(BThi + brow) + cp_p * 16, true);
            cpa16(d + 20480, (const char*)(BTlo + brow) + cp_p * 16, true);
        }
        asm volatile("cp.async.commit_group;");
    };

    const int nchunk = K >> 5;
    prefetch(0);
    for (int ch = 0; ch < nchunk; ch++) {
        if (ch + 1 < nchunk) {
            prefetch(ch + 1);
            asm volatile("cp.async.wait_group 1;");
        } else {
            asm volatile("cp.async.wait_group 0;");
        }
        __syncthreads();

        const uint32_t so = sbase + (uint32_t)(ch & 1) * STAGE_B;
        #pragma unroll
        for (int ks = 0; ks < 2; ks++) {
            uint32_t ah[2][4];
            #pragma unroll
            for (int mt = 0; mt < 2; mt++) {
                uint32_t off = so + (uint32_t)(((a_row_l + mt * 16) * SLDA + a_col_l + ks * 16) * 2);
                ldsm4(ah[mt], off);
            }
            #pragma unroll
            for (int np = 0; np < 4; np++) {
                uint32_t bh[4], bl[4];
                uint32_t off = so + 10240 + (uint32_t)(((b_row_l + np * 16) * SLDA + b_col_l + ks * 16) * 2);
                ldsm4(bh, off);
                ldsm4(bl, off + 10240);
                #pragma unroll
                for (int mt = 0; mt < 2; mt++) {
                    mma_fp16(acc[mt][np * 2],     ah[mt], bh[0], bh[1]);
                    mma_fp16(acc[mt][np * 2],     ah[mt], bl[0], bl[1]);
                    mma_fp16(acc[mt][np * 2 + 1], ah[mt], bh[2], bh[3]);
                    mma_fp16(acc[mt][np * 2 + 1], ah[mt], bl[2], bl[3]);
                }
            }
        }
        __syncthreads();
    }

    // ---- epilogue ----
    #pragma unroll
    for (int mt = 0; mt < 2; mt++) {
        #pragma unroll
        for (int nt = 0; nt < 8; nt++) {
            int gc = col0 + wc + nt * 8 + (lane & 3) * 2;
            #pragma unroll
            for (int g = 0; g < 2; g++) {
                int gr = row0 + wr + mt * 16 + (lane >> 2) + g * 8;
                if (gr < M) {
                    float vx = acc[mt][nt][g * 2];
                    float vy = acc[mt][nt][g * 2 + 1];
                    if (bias != nullptr) {
                        float2 b2 = *(const float2*)(bias + gc);
                        vx += b2.x; vy += b2.y;
                    }
                    if (EPI == 3) {
                        vx = gelu_tanh(vx); vy = gelu_tanh(vy);
                        *(uint32_t*)(Ch + (size_t)gr * N + gc) = pack_h2(vx, vy);
                    } else {
                        if (EPI == 2) {
                            float2 g2 = *(const float2*)(gate + (size_t)gr * 768 + gc);
                            float2 r2 = *(const float2*)(res + (size_t)gr * N + gc);
                            vx = r2.x + g2.x * vx;
                            vy = r2.y + g2.y * vy;
                        }
                        *(float2*)(C + (size_t)gr * N + gc) = make_float2(vx, vy);
                    }
                }
            }
        }
    }
}

// ---------------- launch -------------------------------------------------------
static inline int cdiv(int a, int b) { return (a + b - 1) / b; }

extern "C" void kernel_launch(void* const* d_in, const int* in_sizes, int n_in,
                              void* d_out, int out_size) {
    const float* x      = (const float*)d_in[0];
    const void*  ei     = d_in[1];
    const float* c      = (const float*)d_in[2];
    const float* w_qkv  = (const float*)d_in[3];
    const float* w_proj = (const float*)d_in[4];
    const float* b_proj = (const float*)d_in[5];
    const float* w_mlp1 = (const float*)d_in[6];
    const float* b_mlp1 = (const float*)d_in[7];
    const float* w_mlp2 = (const float*)d_in[8];
    const float* b_mlp2 = (const float*)d_in[9];
    const float* w_ada  = (const float*)d_in[10];
    const float* b_ada  = (const float*)d_in[11];
    float*       out    = (float*)d_out;

    float *mods, *qkv, *x1;
    __half *wthi, *wtlo, *xa, *ha;
    cudaGetSymbolAddress((void**)&mods, g_mods);
    cudaGetSymbolAddress((void**)&qkv,  g_qkv);
    cudaGetSymbolAddress((void**)&x1,   g_x1);
    cudaGetSymbolAddress((void**)&wthi, g_wthi);
    cudaGetSymbolAddress((void**)&wtlo, g_wtlo);
    cudaGetSymbolAddress((void**)&xa,   g_xa);
    cudaGetSymbolAddress((void**)&ha,   g_ha);

    cudaFuncSetAttribute(mma_gemm<0>, cudaFuncAttributeMaxDynamicSharedMemorySize, SM_TOT);
    cudaFuncSetAttribute(mma_gemm<2>, cudaFuncAttributeMaxDynamicSharedMemorySize, SM_TOT);
    cudaFuncSetAttribute(mma_gemm<3>, cudaFuncAttributeMaxDynamicSharedMemorySize, SM_TOT);

    const int MB = cdiv(NNODE, 128);

    detect_kernel<<<1, 256>>>(ei);                                                      // 0
    wsplit_all_kernel<<<cdiv(WTOT, 256), 256>>>(w_ada, w_qkv, w_proj, w_mlp1, w_mlp2);  // 1
    silu_h_kernel<<<cdiv(NNODE * HID / 4, 256), 256>>>(c, xa);                          // 2

    // mods = silu(c) @ w_ada + b_ada            [N, 768]    (launch idx 3: ncu slot)
    mma_gemm<0><<<dim3(768 / 128, MB), 256, SM_TOT>>>(
        xa, wthi + WOFF_ADA, wtlo + WOFF_ADA, b_ada,
        nullptr, nullptr, mods, nullptr, NNODE, 768, HID);

    // CSR build
    convert_kernel<<<cdiv(NEDGE, 256), 256>>>(ei);
    scan_kernel<<<1, 1024>>>();
    scatter_kernel<<<cdiv(NEDGE, 256), 256>>>();

    // xmod = modulate(LN(x), sh_msa, sc_msa) -> fp16
    ln_mod_kernel<<<cdiv(NNODE * 32, 256), 256>>>(x, 0, 128, xa);

    // qkv = xmod @ w_qkv                         [N, 384]
    mma_gemm<0><<<dim3(384 / 128, MB), 256, SM_TOT>>>(
        xa, wthi + WOFF_QKV, wtlo + WOFF_QKV, nullptr,
        nullptr, nullptr, qkv, nullptr, NNODE, 384, HID);

    // dst-major attention -> fp16 (reuse xa)
    dst_attn_kernel<<<cdiv(NNODE * 32, 256), 256>>>(xa);

    // x1 = x + g_msa * (attn @ w_proj + b_proj)
    mma_gemm<2><<<dim3(1, MB), 256, SM_TOT>>>(
        xa, wthi + WOFF_PROJ, wtlo + WOFF_PROJ, b_proj,
        mods + 256, x, x1, nullptr, NNODE, HID, HID);

    // hmod = modulate(LN(x1), sh_mlp, sc_mlp) -> fp16 (reuse xa)
    ln_mod_kernel<<<cdiv(NNODE * 32, 256), 256>>>(x1, 384, 512, xa);

    // h = gelu(hmod @ w_mlp1 + b_mlp1) -> fp16   [N, 512]
    mma_gemm<3><<<dim3(MLPD / 128, MB), 256, SM_TOT>>>(
        xa, wthi + WOFF_MLP1, wtlo + WOFF_MLP1, b_mlp1,
        nullptr, nullptr, nullptr, ha, NNODE, MLPD, HID);

    // out = x1 + g_mlp * (h @ w_mlp2 + b_mlp2)
    mma_gemm<2><<<dim3(1, MB), 256, SM_TOT>>>(
        ha, wthi + WOFF_MLP2, wtlo + WOFF_MLP2, b_mlp2,
        mods + 640, x1, out, nullptr, NNODE, HID, MLPD);
}

// round 14
// speedup vs baseline: 1.7880x; 1.1716x over previous
#include <cuda_runtime.h>
#include <cuda_bf16.h>
#include <cuda_fp16.h>
#include <math_constants.h>
#include <cstdint>

#define HID  128
#define NNODE 50000
#define NEDGE 800000
#define MLPD 512

// ---------------- scratch (static device globals; no runtime alloc) ------------
__device__ __align__(16) float g_mods [(size_t)NNODE * 768];
__device__ __align__(16) float g_qkv  [(size_t)NNODE * 384];
__device__ __align__(16) float g_x1   [(size_t)NNODE * HID];
// fp16 activations
__device__ __align__(16) __half g_xa[(size_t)NNODE * HID];
__device__ __align__(16) __half g_ha[(size_t)NNODE * MLPD];
// CSR (dst-major) edge structure
__device__ int g_src[NEDGE];
__device__ int g_dst[NEDGE];
__device__ int g_psrc[NEDGE];
__device__ int g_cnt[NNODE];
__device__ int g_off[NNODE + 1];
__device__ int g_woff[NNODE];
__device__ int g_is32;

// transposed fp16 weights: WT[N][K], K contiguous
#define WOFF_ADA  0
#define WOFF_QKV  98304
#define WOFF_PROJ 147456
#define WOFF_MLP1 163840
#define WOFF_MLP2 229376
#define WTOT      294912
__device__ __align__(16) __half g_wthi[WTOT];

// ---------------- helpers ------------------------------------------------------
__device__ __forceinline__ float siluf(float v) {
    return v / (1.0f + __expf(-v));
}
__device__ __forceinline__ float gelu_tanh(float v) {
    float v3 = v * v * v;
    float t = tanhf(0.7978845608028654f * (v + 0.044715f * v3));
    return 0.5f * v * (1.0f + t);
}
__device__ __forceinline__ uint32_t smem_u32(const void* p) {
    uint32_t a;
    asm("{ .reg .u64 t; cvta.to.shared.u64 t, %1; cvt.u32.u64 %0, t; }" : "=r"(a) : "l"(p));
    return a;
}
__device__ __forceinline__ void ldsm4(uint32_t* r, uint32_t addr) {
    asm volatile("ldmatrix.sync.aligned.m8n8.x4.shared.b16 {%0,%1,%2,%3}, [%4];"
                 : "=r"(r[0]), "=r"(r[1]), "=r"(r[2]), "=r"(r[3]) : "r"(addr));
}
__device__ __forceinline__ void mma_fp16(float* d, const uint32_t* a,
                                         uint32_t b0, uint32_t b1) {
    asm volatile(
        "mma.sync.aligned.m16n8k16.row.col.f32.f16.f16.f32 "
        "{%0,%1,%2,%3}, {%4,%5,%6,%7}, {%8,%9}, {%0,%1,%2,%3};"
        : "+f"(d[0]), "+f"(d[1]), "+f"(d[2]), "+f"(d[3])
        : "r"(a[0]), "r"(a[1]), "r"(a[2]), "r"(a[3]), "r"(b0), "r"(b1));
}
__device__ __forceinline__ uint32_t pack_h2(float x, float y) {
    __half2 h = __floats2half2_rn(x, y);
    uint32_t r;
    memcpy(&r, &h, 4);
    return r;
}
__device__ __forceinline__ void cpa16(uint32_t dst, const void* src, bool valid) {
    int sz = valid ? 16 : 0;
    asm volatile("cp.async.cg.shared.global [%0], [%1], 16, %2;"
                 :: "r"(dst), "l"(src), "r"(sz));
}

// ---------------- edge-index dtype detection + cnt zero ------------------------
__global__ void detect_kernel(const void* ei_raw) {
    const long long* p = (const long long*)ei_raw;
    int bad = 0;
    for (int i = threadIdx.x; i < 256; i += blockDim.x) {
        long long v = p[i];
        if (v < 0 || v >= NNODE) bad = 1;
    }
    bad = __syncthreads_or(bad);
    if (threadIdx.x == 0) g_is32 = bad;
    for (int i = threadIdx.x; i < NNODE; i += blockDim.x) g_cnt[i] = 0;
}

// ---------------- convert + dst histogram --------------------------------------
__global__ void convert_kernel(const void* ei_raw) {
    int e = blockIdx.x * blockDim.x + threadIdx.x;
    if (e >= NEDGE) return;
    int s, d;
    if (g_is32) {
        const int* p = (const int*)ei_raw;
        s = p[e]; d = p[NEDGE + e];
    } else {
        const long long* p = (const long long*)ei_raw;
        s = (int)p[e]; d = (int)p[NEDGE + e];
    }
    g_src[e] = s;
    g_dst[e] = d;
    atomicAdd(&g_cnt[d], 1);
}

// ---------------- single-block exclusive scan over g_cnt -----------------------
__global__ void scan_kernel() {
    const int tid  = threadIdx.x;
    const int lane = tid & 31, wid = tid >> 5;
    __shared__ int wsum[32];
    __shared__ int s_carry;
    if (tid == 0) s_carry = 0;
    __syncthreads();
    for (int base = 0; base < NNODE; base += 1024) {
        int i = base + tid;
        int v = (i < NNODE) ? g_cnt[i] : 0;
        int x = v;
        #pragma unroll
        for (int o = 1; o < 32; o <<= 1) {
            int t = __shfl_up_sync(0xffffffffu, x, o);
            if (lane >= o) x += t;
        }
        if (lane == 31) wsum[wid] = x;
        __syncthreads();
        if (wid == 0) {
            int y = wsum[lane];
            #pragma unroll
            for (int o = 1; o < 32; o <<= 1) {
                int t = __shfl_up_sync(0xffffffffu, y, o);
                if (lane >= o) y += t;
            }
            wsum[lane] = y;
        }
        __syncthreads();
        int warp_excl = (wid == 0) ? 0 : wsum[wid - 1];
        int incl = x + warp_excl;
        int carry = s_carry;
        if (i < NNODE) {
            g_off[i]  = carry + incl - v;
            g_woff[i] = carry + incl - v;
        }
        __syncthreads();
        if (tid == 1023) s_carry = carry + incl;
        __syncthreads();
    }
    if (tid == 0) g_off[NNODE] = s_carry;
}

// ---------------- scatter src ids into dst-major order -------------------------
__global__ void scatter_kernel() {
    int e = blockIdx.x * blockDim.x + threadIdx.x;
    if (e >= NEDGE) return;
    int pos = atomicAdd(&g_woff[g_dst[e]], 1);
    g_psrc[pos] = g_src[e];
}

// ---------------- ALL weight transposes -> fp16 in one kernel ------------------
__global__ void wsplit_all_kernel(const float* __restrict__ w_ada,
                                  const float* __restrict__ w_qkv,
                                  const float* __restrict__ w_proj,
                                  const float* __restrict__ w_mlp1,
                                  const float* __restrict__ w_mlp2) {
    int t = blockIdx.x * blockDim.x + threadIdx.x;
    if (t >= WTOT) return;
    const float* W;
    int Kg, Ng, l;
    if (t < WOFF_QKV)       { W = w_ada;  Kg = 128; Ng = 768; l = t - WOFF_ADA; }
    else if (t < WOFF_PROJ) { W = w_qkv;  Kg = 128; Ng = 384; l = t - WOFF_QKV; }
    else if (t < WOFF_MLP1) { W = w_proj; Kg = 128; Ng = 128; l = t - WOFF_PROJ; }
    else if (t < WOFF_MLP2) { W = w_mlp1; Kg = 128; Ng = 512; l = t - WOFF_MLP1; }
    else                    { W = w_mlp2; Kg = 512; Ng = 128; l = t - WOFF_MLP2; }
    int n = l / Kg, k = l % Kg;
    g_wthi[t] = __float2half_rn(W[(size_t)k * Ng + n]);
}

// ---------------- silu(c) -> fp16 ----------------------------------------------
__global__ void silu_h_kernel(const float* __restrict__ c,
                              __half* __restrict__ o) {
    int t4 = blockIdx.x * blockDim.x + threadIdx.x;
    if (t4 >= NNODE * HID / 4) return;
    float4 v = ((const float4*)c)[t4];
    uint32_t a = pack_h2(siluf(v.x), siluf(v.y));
    uint32_t b = pack_h2(siluf(v.z), siluf(v.w));
    *(uint2*)(o + (size_t)t4 * 4) = make_uint2(a, b);
}

// ---------------- LayerNorm + modulate -> fp16 ---------------------------------
__global__ void ln_mod_kernel(const float* __restrict__ X,
                              int shift_off, int scale_off,
                              __half* __restrict__ o) {
    int warp = (blockIdx.x * blockDim.x + threadIdx.x) >> 5;
    if (warp >= NNODE) return;
    int lane = threadIdx.x & 31;
    const float4 v = *(const float4*)(X + (size_t)warp * HID + lane * 4);
    float s  = v.x + v.y + v.z + v.w;
    float sq = v.x * v.x + v.y * v.y + v.z * v.z + v.w * v.w;
    #pragma unroll
    for (int oo = 16; oo > 0; oo >>= 1) {
        s  += __shfl_xor_sync(0xffffffffu, s,  oo);
        sq += __shfl_xor_sync(0xffffffffu, sq, oo);
    }
    float mean = s * (1.0f / HID);
    float var  = sq * (1.0f / HID) - mean * mean;
    float rstd = rsqrtf(var + 1e-6f);
    const float4 sh = *(const float4*)(g_mods + (size_t)warp * 768 + shift_off + lane * 4);
    const float4 sc = *(const float4*)(g_mods + (size_t)warp * 768 + scale_off + lane * 4);
    float ox = (v.x - mean) * rstd * (1.0f + sc.x) + sh.x;
    float oy = (v.y - mean) * rstd * (1.0f + sc.y) + sh.y;
    float oz = (v.z - mean) * rstd * (1.0f + sc.z) + sh.z;
    float ow = (v.w - mean) * rstd * (1.0f + sc.w) + sh.w;
    *(uint2*)(o + (size_t)warp * HID + lane * 4) =
        make_uint2(pack_h2(ox, oy), pack_h2(oz, ow));
}

// ---------------- dst-major attention -> fp16 ----------------------------------
__global__ void dst_attn_kernel(__half* __restrict__ o) {
    int d = (blockIdx.x * blockDim.x + threadIdx.x) >> 5;
    if (d >= NNODE) return;
    int lane = threadIdx.x & 31;
    const float4 q = *(const float4*)(g_qkv + (size_t)d * 384 + lane * 4);
    float4 acc = make_float4(0.f, 0.f, 0.f, 0.f);
    float den = 0.0f;
    const int b = g_off[d], e = g_off[d + 1];
    for (int i = b; i < e; i++) {
        int src = g_psrc[i];
        const float4 k = *(const float4*)(g_qkv + (size_t)src * 384 + 128 + lane * 4);
        const float4 v = *(const float4*)(g_qkv + (size_t)src * 384 + 256 + lane * 4);
        float p = q.x * k.x + q.y * k.y + q.z * k.z + q.w * k.w;
        p += __shfl_xor_sync(0xffffffffu, p, 1);
        p += __shfl_xor_sync(0xffffffffu, p, 2);
        float ex = __expf(p * 0.25f);
        acc.x += ex * v.x; acc.y += ex * v.y;
        acc.z += ex * v.z; acc.w += ex * v.w;
        den += ex;
    }
    float wn = (den > 0.0f) ? (1.0f / den) : 0.0f;
    *(uint2*)(o + (size_t)d * HID + lane * 4) =
        make_uint2(pack_h2(acc.x * wn, acc.y * wn), pack_h2(acc.z * wn, acc.w * wn));
}

// ---------------- fp16 mma.sync GEMM, cp.async 3-stage pipeline ----------------
// A fp16 [M,K]; B fp16 [N,K].  fp32 accumulate.
// EPI: 0=none 2=res+gate*(acc+bias) 3=gelu->fp16 (Ch)
#define SLDA 40
#define STAGE_B 20480      // 2 * 128 * 40 * 2
#define SM_TOT  61440      // 3 stages
template<int EPI>
__global__ __launch_bounds__(256, 2)
void mma_gemm(const __half* __restrict__ Af,
              const __half* __restrict__ BT,
              const float* __restrict__ bias,
              const float* __restrict__ gate,   // row stride 768 (EPI==2)
              const float* __restrict__ res,    // row stride N   (EPI==2)
              float* __restrict__ C,
              __half* __restrict__ Ch,          // EPI==3
              int M, int N, int K) {
    extern __shared__ char smem[];
    const uint32_t sbase = smem_u32(smem);

    const int tid  = threadIdx.x;
    const int lane = tid & 31;
    const int w    = tid >> 5;
    const int row0 = blockIdx.y * 128;
    const int col0 = blockIdx.x * 128;
    const int wr   = (w >> 1) * 32;
    const int wc   = (w & 1) * 64;

    float acc[2][8][4];
    #pragma unroll
    for (int i = 0; i < 2; i++)
        #pragma unroll
        for (int j = 0; j < 8; j++)
            #pragma unroll
            for (int q = 0; q < 4; q++) acc[i][j][q] = 0.0f;

    const int a_row_l = wr + (lane & 15);
    const int a_col_l = (lane >> 4) * 8;
    const int b_row_l = wc + ((lane >> 4) & 1) * 8 + (lane & 7);
    const int b_col_l = ((lane >> 3) & 1) * 8;

    const int cp_r0 = tid >> 2, cp_p = (tid & 3);

    auto prefetch = [&](int ch) {
        const int k0 = ch * 32;
        const uint32_t so = sbase + (uint32_t)(ch % 3) * STAGE_B;
        #pragma unroll
        for (int i = 0; i < 2; i++) {
            int r = cp_r0 + i * 64;
            int gr = row0 + r;
            bool ok = gr < M;
            const size_t arow = (size_t)(ok ? gr : 0) * K + k0;
            uint32_t d = so + (uint32_t)(r * 80 + cp_p * 16);
            cpa16(d, (const char*)(Af + arow) + cp_p * 16, ok);
            const size_t brow = (size_t)(col0 + r) * K + k0;
            cpa16(d + 10240, (const char*)(BT + brow) + cp_p * 16, true);
        }
        asm volatile("cp.async.commit_group;");
    };

    const int nchunk = K >> 5;
    prefetch(0);
    if (nchunk > 1) prefetch(1);
    for (int ch = 0; ch < nchunk; ch++) {
        if (ch + 2 < nchunk) {
            prefetch(ch + 2);
            asm volatile("cp.async.wait_group 2;");
        } else if (ch + 1 < nchunk) {
            asm volatile("cp.async.wait_group 1;");
        } else {
            asm volatile("cp.async.wait_group 0;");
        }
        __syncthreads();

        const uint32_t so = sbase + (uint32_t)(ch % 3) * STAGE_B;
        #pragma unroll
        for (int ks = 0; ks < 2; ks++) {
            uint32_t ah[2][4];
            #pragma unroll
            for (int mt = 0; mt < 2; mt++) {
                uint32_t off = so + (uint32_t)(((a_row_l + mt * 16) * SLDA + a_col_l + ks * 16) * 2);
                ldsm4(ah[mt], off);
            }
            #pragma unroll
            for (int np = 0; np < 4; np++) {
                uint32_t bh[4];
                uint32_t off = so + 10240 + (uint32_t)(((b_row_l + np * 16) * SLDA + b_col_l + ks * 16) * 2);
                ldsm4(bh, off);
                #pragma unroll
                for (int mt = 0; mt < 2; mt++) {
                    mma_fp16(acc[mt][np * 2],     ah[mt], bh[0], bh[1]);
                    mma_fp16(acc[mt][np * 2 + 1], ah[mt], bh[2], bh[3]);
                }
            }
        }
        __syncthreads();
    }

    // ---- epilogue ----
    #pragma unroll
    for (int mt = 0; mt < 2; mt++) {
        #pragma unroll
        for (int nt = 0; nt < 8; nt++) {
            int gc = col0 + wc + nt * 8 + (lane & 3) * 2;
            #pragma unroll
            for (int g = 0; g < 2; g++) {
                int gr = row0 + wr + mt * 16 + (lane >> 2) + g * 8;
                if (gr < M) {
                    float vx = acc[mt][nt][g * 2];
                    float vy = acc[mt][nt][g * 2 + 1];
                    if (bias != nullptr) {
                        float2 b2 = *(const float2*)(bias + gc);
                        vx += b2.x; vy += b2.y;
                    }
                    if (EPI == 3) {
                        vx = gelu_tanh(vx); vy = gelu_tanh(vy);
                        *(uint32_t*)(Ch + (size_t)gr * N + gc) = pack_h2(vx, vy);
                    } else {
                        if (EPI == 2) {
                            float2 g2 = *(const float2*)(gate + (size_t)gr * 768 + gc);
                            float2 r2 = *(const float2*)(res + (size_t)gr * N + gc);
                            vx = r2.x + g2.x * vx;
                            vy = r2.y + g2.y * vy;
                        }
                        *(float2*)(C + (size_t)gr * N + gc) = make_float2(vx, vy);
                    }
                }
            }
        }
    }
}

// ---------------- launch -------------------------------------------------------
static inline int cdiv(int a, int b) { return (a + b - 1) / b; }

extern "C" void kernel_launch(void* const* d_in, const int* in_sizes, int n_in,
                              void* d_out, int out_size) {
    const float* x      = (const float*)d_in[0];
    const void*  ei     = d_in[1];
    const float* c      = (const float*)d_in[2];
    const float* w_qkv  = (const float*)d_in[3];
    const float* w_proj = (const float*)d_in[4];
    const float* b_proj = (const float*)d_in[5];
    const float* w_mlp1 = (const float*)d_in[6];
    const float* b_mlp1 = (const float*)d_in[7];
    const float* w_mlp2 = (const float*)d_in[8];
    const float* b_mlp2 = (const float*)d_in[9];
    const float* w_ada  = (const float*)d_in[10];
    const float* b_ada  = (const float*)d_in[11];
    float*       out    = (float*)d_out;

    float *mods, *qkv, *x1;
    __half *wthi, *xa, *ha;
    cudaGetSymbolAddress((void**)&mods, g_mods);
    cudaGetSymbolAddress((void**)&qkv,  g_qkv);
    cudaGetSymbolAddress((void**)&x1,   g_x1);
    cudaGetSymbolAddress((void**)&wthi, g_wthi);
    cudaGetSymbolAddress((void**)&xa,   g_xa);
    cudaGetSymbolAddress((void**)&ha,   g_ha);

    cudaFuncSetAttribute(mma_gemm<0>, cudaFuncAttributeMaxDynamicSharedMemorySize, SM_TOT);
    cudaFuncSetAttribute(mma_gemm<2>, cudaFuncAttributeMaxDynamicSharedMemorySize, SM_TOT);
    cudaFuncSetAttribute(mma_gemm<3>, cudaFuncAttributeMaxDynamicSharedMemorySize, SM_TOT);

    const int MB = cdiv(NNODE, 128);

    detect_kernel<<<1, 256>>>(ei);                                                      // 0
    wsplit_all_kernel<<<cdiv(WTOT, 256), 256>>>(w_ada, w_qkv, w_proj, w_mlp1, w_mlp2);  // 1
    silu_h_kernel<<<cdiv(NNODE * HID / 4, 256), 256>>>(c, xa);                          // 2

    // mods = silu(c) @ w_ada + b_ada            [N, 768]    (launch idx 3: ncu slot)
    mma_gemm<0><<<dim3(768 / 128, MB), 256, SM_TOT>>>(
        xa, wthi + WOFF_ADA, b_ada, nullptr, nullptr, mods, nullptr, NNODE, 768, HID);

    // CSR build
    convert_kernel<<<cdiv(NEDGE, 256), 256>>>(ei);
    scan_kernel<<<1, 1024>>>();
    scatter_kernel<<<cdiv(NEDGE, 256), 256>>>();

    // xmod = modulate(LN(x), sh_msa, sc_msa) -> fp16
    ln_mod_kernel<<<cdiv(NNODE * 32, 256), 256>>>(x, 0, 128, xa);

    // qkv = xmod @ w_qkv                         [N, 384]
    mma_gemm<0><<<dim3(384 / 128, MB), 256, SM_TOT>>>(
        xa, wthi + WOFF_QKV, nullptr, nullptr, nullptr, qkv, nullptr, NNODE, 384, HID);

    // dst-major attention -> fp16 (reuse xa)
    dst_attn_kernel<<<cdiv(NNODE * 32, 256), 256>>>(xa);

    // x1 = x + g_msa * (attn @ w_proj + b_proj)
    mma_gemm<2><<<dim3(1, MB), 256, SM_TOT>>>(
        xa, wthi + WOFF_PROJ, b_proj, mods + 256, x, x1, nullptr, NNODE, HID, HID);

    // hmod = modulate(LN(x1), sh_mlp, sc_mlp) -> fp16 (reuse xa)
    ln_mod_kernel<<<cdiv(NNODE * 32, 256), 256>>>(x1, 384, 512, xa);

    // h = gelu(hmod @ w_mlp1 + b_mlp1) -> fp16   [N, 512]
    mma_gemm<3><<<dim3(MLPD / 128, MB), 256, SM_TOT>>>(
        xa, wthi + WOFF_MLP1, b_mlp1, nullptr, nullptr, nullptr, ha, NNODE, MLPD, HID);

    // out = x1 + g_mlp * (h @ w_mlp2 + b_mlp2)
    mma_gemm<2><<<dim3(1, MB), 256, SM_TOT>>>(
        ha, wthi + WOFF_MLP2, b_mlp2, mods + 640, x1, out, nullptr, NNODE, HID, MLPD);
}

// round 15
// speedup vs baseline: 1.8225x; 1.0193x over previous
#include <cuda_runtime.h>
#include <cuda_bf16.h>
#include <cuda_fp16.h>
#include <math_constants.h>
#include <cstdint>

#define HID  128
#define NNODE 50000
#define NEDGE 800000
#define MLPD 512

// ---------------- scratch (static device globals; no runtime alloc) ------------
__device__ __align__(16) float g_mods [(size_t)NNODE * 768];
__device__ __align__(16) float g_x1   [(size_t)NNODE * HID];
// fp16 activations
__device__ __align__(16) __half g_qkvh[(size_t)NNODE * 384];
__device__ __align__(16) __half g_xa[(size_t)NNODE * HID];
__device__ __align__(16) __half g_ha[(size_t)NNODE * MLPD];
// CSR (dst-major) edge structure
__device__ int g_src[NEDGE];
__device__ int g_dst[NEDGE];
__device__ int g_psrc[NEDGE];
__device__ int g_cnt[NNODE];
__device__ int g_off[NNODE + 1];
__device__ int g_woff[NNODE];
__device__ int g_is32;

// transposed fp16 weights: WT[N][K], K contiguous
#define WOFF_ADA  0
#define WOFF_QKV  98304
#define WOFF_PROJ 147456
#define WOFF_MLP1 163840
#define WOFF_MLP2 229376
#define WTOT      294912
__device__ __align__(16) __half g_wthi[WTOT];

// ---------------- helpers ------------------------------------------------------
__device__ __forceinline__ float siluf(float v) {
    return v / (1.0f + __expf(-v));
}
__device__ __forceinline__ float gelu_tanh(float v) {
    float v3 = v * v * v;
    float t = tanhf(0.7978845608028654f * (v + 0.044715f * v3));
    return 0.5f * v * (1.0f + t);
}
__device__ __forceinline__ uint32_t smem_u32(const void* p) {
    uint32_t a;
    asm("{ .reg .u64 t; cvta.to.shared.u64 t, %1; cvt.u32.u64 %0, t; }" : "=r"(a) : "l"(p));
    return a;
}
__device__ __forceinline__ void ldsm4(uint32_t* r, uint32_t addr) {
    asm volatile("ldmatrix.sync.aligned.m8n8.x4.shared.b16 {%0,%1,%2,%3}, [%4];"
                 : "=r"(r[0]), "=r"(r[1]), "=r"(r[2]), "=r"(r[3]) : "r"(addr));
}
__device__ __forceinline__ void mma_fp16(float* d, const uint32_t* a,
                                         uint32_t b0, uint32_t b1) {
    asm volatile(
        "mma.sync.aligned.m16n8k16.row.col.f32.f16.f16.f32 "
        "{%0,%1,%2,%3}, {%4,%5,%6,%7}, {%8,%9}, {%0,%1,%2,%3};"
        : "+f"(d[0]), "+f"(d[1]), "+f"(d[2]), "+f"(d[3])
        : "r"(a[0]), "r"(a[1]), "r"(a[2]), "r"(a[3]), "r"(b0), "r"(b1));
}
__device__ __forceinline__ uint32_t pack_h2(float x, float y) {
    __half2 h = __floats2half2_rn(x, y);
    uint32_t r;
    memcpy(&r, &h, 4);
    return r;
}
// load 4 halves as 2 float2s
__device__ __forceinline__ float4 ld_h4(const __half* p) {
    uint2 u = *(const uint2*)p;
    __half2 a, b;
    memcpy(&a, &u.x, 4);
    memcpy(&b, &u.y, 4);
    float2 fa = __half22float2(a), fb = __half22float2(b);
    return make_float4(fa.x, fa.y, fb.x, fb.y);
}
__device__ __forceinline__ void cpa16(uint32_t dst, const void* src, bool valid) {
    int sz = valid ? 16 : 0;
    asm volatile("cp.async.cg.shared.global [%0], [%1], 16, %2;"
                 :: "r"(dst), "l"(src), "r"(sz));
}

// ---------------- edge-index dtype detection + cnt zero ------------------------
__global__ void detect_kernel(const void* ei_raw) {
    const long long* p = (const long long*)ei_raw;
    int bad = 0;
    for (int i = threadIdx.x; i < 256; i += blockDim.x) {
        long long v = p[i];
        if (v < 0 || v >= NNODE) bad = 1;
    }
    bad = __syncthreads_or(bad);
    if (threadIdx.x == 0) g_is32 = bad;
    for (int i = threadIdx.x; i < NNODE; i += blockDim.x) g_cnt[i] = 0;
}

// ---------------- convert + dst histogram --------------------------------------
__global__ void convert_kernel(const void* ei_raw) {
    int e = blockIdx.x * blockDim.x + threadIdx.x;
    if (e >= NEDGE) return;
    int s, d;
    if (g_is32) {
        const int* p = (const int*)ei_raw;
        s = p[e]; d = p[NEDGE + e];
    } else {
        const long long* p = (const long long*)ei_raw;
        s = (int)p[e]; d = (int)p[NEDGE + e];
    }
    g_src[e] = s;
    g_dst[e] = d;
    atomicAdd(&g_cnt[d], 1);
}

// ---------------- single-block exclusive scan over g_cnt -----------------------
__global__ void scan_kernel() {
    const int tid  = threadIdx.x;
    const int lane = tid & 31, wid = tid >> 5;
    __shared__ int wsum[32];
    __shared__ int s_carry;
    if (tid == 0) s_carry = 0;
    __syncthreads();
    for (int base = 0; base < NNODE; base += 1024) {
        int i = base + tid;
        int v = (i < NNODE) ? g_cnt[i] : 0;
        int x = v;
        #pragma unroll
        for (int o = 1; o < 32; o <<= 1) {
            int t = __shfl_up_sync(0xffffffffu, x, o);
            if (lane >= o) x += t;
        }
        if (lane == 31) wsum[wid] = x;
        __syncthreads();
        if (wid == 0) {
            int y = wsum[lane];
            #pragma unroll
            for (int o = 1; o < 32; o <<= 1) {
                int t = __shfl_up_sync(0xffffffffu, y, o);
                if (lane >= o) y += t;
            }
            wsum[lane] = y;
        }
        __syncthreads();
        int warp_excl = (wid == 0) ? 0 : wsum[wid - 1];
        int incl = x + warp_excl;
        int carry = s_carry;
        if (i < NNODE) {
            g_off[i]  = carry + incl - v;
            g_woff[i] = carry + incl - v;
        }
        __syncthreads();
        if (tid == 1023) s_carry = carry + incl;
        __syncthreads();
    }
    if (tid == 0) g_off[NNODE] = s_carry;
}

// ---------------- scatter src ids into dst-major order -------------------------
__global__ void scatter_kernel() {
    int e = blockIdx.x * blockDim.x + threadIdx.x;
    if (e >= NEDGE) return;
    int pos = atomicAdd(&g_woff[g_dst[e]], 1);
    g_psrc[pos] = g_src[e];
}

// ---------------- ALL weight transposes -> fp16 in one kernel ------------------
__global__ void wsplit_all_kernel(const float* __restrict__ w_ada,
                                  const float* __restrict__ w_qkv,
                                  const float* __restrict__ w_proj,
                                  const float* __restrict__ w_mlp1,
                                  const float* __restrict__ w_mlp2) {
    int t = blockIdx.x * blockDim.x + threadIdx.x;
    if (t >= WTOT) return;
    const float* W;
    int Kg, Ng, l;
    if (t < WOFF_QKV)       { W = w_ada;  Kg = 128; Ng = 768; l = t - WOFF_ADA; }
    else if (t < WOFF_PROJ) { W = w_qkv;  Kg = 128; Ng = 384; l = t - WOFF_QKV; }
    else if (t < WOFF_MLP1) { W = w_proj; Kg = 128; Ng = 128; l = t - WOFF_PROJ; }
    else if (t < WOFF_MLP2) { W = w_mlp1; Kg = 128; Ng = 512; l = t - WOFF_MLP1; }
    else                    { W = w_mlp2; Kg = 512; Ng = 128; l = t - WOFF_MLP2; }
    int n = l / Kg, k = l % Kg;
    g_wthi[t] = __float2half_rn(W[(size_t)k * Ng + n]);
}

// ---------------- silu(c) -> fp16 ----------------------------------------------
__global__ void silu_h_kernel(const float* __restrict__ c,
                              __half* __restrict__ o) {
    int t4 = blockIdx.x * blockDim.x + threadIdx.x;
    if (t4 >= NNODE * HID / 4) return;
    float4 v = ((const float4*)c)[t4];
    uint32_t a = pack_h2(siluf(v.x), siluf(v.y));
    uint32_t b = pack_h2(siluf(v.z), siluf(v.w));
    *(uint2*)(o + (size_t)t4 * 4) = make_uint2(a, b);
}

// ---------------- LayerNorm + modulate -> fp16 ---------------------------------
__global__ void ln_mod_kernel(const float* __restrict__ X,
                              int shift_off, int scale_off,
                              __half* __restrict__ o) {
    int warp = (blockIdx.x * blockDim.x + threadIdx.x) >> 5;
    if (warp >= NNODE) return;
    int lane = threadIdx.x & 31;
    const float4 v = *(const float4*)(X + (size_t)warp * HID + lane * 4);
    float s  = v.x + v.y + v.z + v.w;
    float sq = v.x * v.x + v.y * v.y + v.z * v.z + v.w * v.w;
    #pragma unroll
    for (int oo = 16; oo > 0; oo >>= 1) {
        s  += __shfl_xor_sync(0xffffffffu, s,  oo);
        sq += __shfl_xor_sync(0xffffffffu, sq, oo);
    }
    float mean = s * (1.0f / HID);
    float var  = sq * (1.0f / HID) - mean * mean;
    float rstd = rsqrtf(var + 1e-6f);
    const float4 sh = *(const float4*)(g_mods + (size_t)warp * 768 + shift_off + lane * 4);
    const float4 sc = *(const float4*)(g_mods + (size_t)warp * 768 + scale_off + lane * 4);
    float ox = (v.x - mean) * rstd * (1.0f + sc.x) + sh.x;
    float oy = (v.y - mean) * rstd * (1.0f + sc.y) + sh.y;
    float oz = (v.z - mean) * rstd * (1.0f + sc.z) + sh.z;
    float ow = (v.w - mean) * rstd * (1.0f + sc.w) + sh.w;
    *(uint2*)(o + (size_t)warp * HID + lane * 4) =
        make_uint2(pack_h2(ox, oy), pack_h2(oz, ow));
}

// ---------------- dst-major attention (fp16 qkv, unroll x2) -> fp16 ------------
__global__ void dst_attn_kernel(__half* __restrict__ o) {
    int d = (blockIdx.x * blockDim.x + threadIdx.x) >> 5;
    if (d >= NNODE) return;
    int lane = threadIdx.x & 31;
    const float4 q = ld_h4(g_qkvh + (size_t)d * 384 + lane * 4);
    float4 acc = make_float4(0.f, 0.f, 0.f, 0.f);
    float den = 0.0f;
    const int b = g_off[d], e = g_off[d + 1];
    int i = b;
    for (; i + 2 <= e; i += 2) {
        int s0 = g_psrc[i], s1 = g_psrc[i + 1];
        const float4 k0 = ld_h4(g_qkvh + (size_t)s0 * 384 + 128 + lane * 4);
        const float4 v0 = ld_h4(g_qkvh + (size_t)s0 * 384 + 256 + lane * 4);
        const float4 k1 = ld_h4(g_qkvh + (size_t)s1 * 384 + 128 + lane * 4);
        const float4 v1 = ld_h4(g_qkvh + (size_t)s1 * 384 + 256 + lane * 4);
        float p0 = q.x * k0.x + q.y * k0.y + q.z * k0.z + q.w * k0.w;
        float p1 = q.x * k1.x + q.y * k1.y + q.z * k1.z + q.w * k1.w;
        p0 += __shfl_xor_sync(0xffffffffu, p0, 1);
        p1 += __shfl_xor_sync(0xffffffffu, p1, 1);
        p0 += __shfl_xor_sync(0xffffffffu, p0, 2);
        p1 += __shfl_xor_sync(0xffffffffu, p1, 2);
        float e0 = __expf(p0 * 0.25f);
        float e1 = __expf(p1 * 0.25f);
        acc.x += e0 * v0.x + e1 * v1.x;
        acc.y += e0 * v0.y + e1 * v1.y;
        acc.z += e0 * v0.z + e1 * v1.z;
        acc.w += e0 * v0.w + e1 * v1.w;
        den += e0 + e1;
    }
    if (i < e) {
        int s0 = g_psrc[i];
        const float4 k0 = ld_h4(g_qkvh + (size_t)s0 * 384 + 128 + lane * 4);
        const float4 v0 = ld_h4(g_qkvh + (size_t)s0 * 384 + 256 + lane * 4);
        float p0 = q.x * k0.x + q.y * k0.y + q.z * k0.z + q.w * k0.w;
        p0 += __shfl_xor_sync(0xffffffffu, p0, 1);
        p0 += __shfl_xor_sync(0xffffffffu, p0, 2);
        float e0 = __expf(p0 * 0.25f);
        acc.x += e0 * v0.x; acc.y += e0 * v0.y;
        acc.z += e0 * v0.z; acc.w += e0 * v0.w;
        den += e0;
    }
    float wn = (den > 0.0f) ? (1.0f / den) : 0.0f;
    *(uint2*)(o + (size_t)d * HID + lane * 4) =
        make_uint2(pack_h2(acc.x * wn, acc.y * wn), pack_h2(acc.z * wn, acc.w * wn));
}

// ---------------- fp16 mma.sync GEMM, cp.async 3-stage pipeline ----------------
// A fp16 [M,K]; B fp16 [N,K].  fp32 accumulate.
// EPI: 0=none 2=res+gate*(acc+bias) 3=gelu->fp16 (Ch) 4=fp16 (Ch), no act
#define SLDA 40
#define STAGE_B 20480      // 2 * 128 * 40 * 2
#define SM_TOT  61440      // 3 stages
template<int EPI>
__global__ __launch_bounds__(256, 2)
void mma_gemm(const __half* __restrict__ Af,
              const __half* __restrict__ BT,
              const float* __restrict__ bias,
              const float* __restrict__ gate,   // row stride 768 (EPI==2)
              const float* __restrict__ res,    // row stride N   (EPI==2)
              float* __restrict__ C,
              __half* __restrict__ Ch,          // EPI==3/4
              int M, int N, int K) {
    extern __shared__ char smem[];
    const uint32_t sbase = smem_u32(smem);

    const int tid  = threadIdx.x;
    const int lane = tid & 31;
    const int w    = tid >> 5;
    const int row0 = blockIdx.y * 128;
    const int col0 = blockIdx.x * 128;
    const int wr   = (w >> 1) * 32;
    const int wc   = (w & 1) * 64;

    float acc[2][8][4];
    #pragma unroll
    for (int i = 0; i < 2; i++)
        #pragma unroll
        for (int j = 0; j < 8; j++)
            #pragma unroll
            for (int q = 0; q < 4; q++) acc[i][j][q] = 0.0f;

    const int a_row_l = wr + (lane & 15);
    const int a_col_l = (lane >> 4) * 8;
    const int b_row_l = wc + ((lane >> 4) & 1) * 8 + (lane & 7);
    const int b_col_l = ((lane >> 3) & 1) * 8;

    const int cp_r0 = tid >> 2, cp_p = (tid & 3);

    auto prefetch = [&](int ch) {
        const int k0 = ch * 32;
        const uint32_t so = sbase + (uint32_t)(ch % 3) * STAGE_B;
        #pragma unroll
        for (int i = 0; i < 2; i++) {
            int r = cp_r0 + i * 64;
            int gr = row0 + r;
            bool ok = gr < M;
            const size_t arow = (size_t)(ok ? gr : 0) * K + k0;
            uint32_t d = so + (uint32_t)(r * 80 + cp_p * 16);
            cpa16(d, (const char*)(Af + arow) + cp_p * 16, ok);
            const size_t brow = (size_t)(col0 + r) * K + k0;
            cpa16(d + 10240, (const char*)(BT + brow) + cp_p * 16, true);
        }
        asm volatile("cp.async.commit_group;");
    };

    const int nchunk = K >> 5;
    prefetch(0);
    if (nchunk > 1) prefetch(1);
    for (int ch = 0; ch < nchunk; ch++) {
        if (ch + 2 < nchunk) {
            prefetch(ch + 2);
            asm volatile("cp.async.wait_group 2;");
        } else if (ch + 1 < nchunk) {
            asm volatile("cp.async.wait_group 1;");
        } else {
            asm volatile("cp.async.wait_group 0;");
        }
        __syncthreads();

        const uint32_t so = sbase + (uint32_t)(ch % 3) * STAGE_B;
        #pragma unroll
        for (int ks = 0; ks < 2; ks++) {
            uint32_t ah[2][4];
            #pragma unroll
            for (int mt = 0; mt < 2; mt++) {
                uint32_t off = so + (uint32_t)(((a_row_l + mt * 16) * SLDA + a_col_l + ks * 16) * 2);
                ldsm4(ah[mt], off);
            }
            #pragma unroll
            for (int np = 0; np < 4; np++) {
                uint32_t bh[4];
                uint32_t off = so + 10240 + (uint32_t)(((b_row_l + np * 16) * SLDA + b_col_l + ks * 16) * 2);
                ldsm4(bh, off);
                #pragma unroll
                for (int mt = 0; mt < 2; mt++) {
                    mma_fp16(acc[mt][np * 2],     ah[mt], bh[0], bh[1]);
                    mma_fp16(acc[mt][np * 2 + 1], ah[mt], bh[2], bh[3]);
                }
            }
        }
        __syncthreads();
    }

    // ---- epilogue ----
    #pragma unroll
    for (int mt = 0; mt < 2; mt++) {
        #pragma unroll
        for (int nt = 0; nt < 8; nt++) {
            int gc = col0 + wc + nt * 8 + (lane & 3) * 2;
            #pragma unroll
            for (int g = 0; g < 2; g++) {
                int gr = row0 + wr + mt * 16 + (lane >> 2) + g * 8;
                if (gr < M) {
                    float vx = acc[mt][nt][g * 2];
                    float vy = acc[mt][nt][g * 2 + 1];
                    if (bias != nullptr) {
                        float2 b2 = *(const float2*)(bias + gc);
                        vx += b2.x; vy += b2.y;
                    }
                    if (EPI == 3 || EPI == 4) {
                        if (EPI == 3) { vx = gelu_tanh(vx); vy = gelu_tanh(vy); }
                        *(uint32_t*)(Ch + (size_t)gr * N + gc) = pack_h2(vx, vy);
                    } else {
                        if (EPI == 2) {
                            float2 g2 = *(const float2*)(gate + (size_t)gr * 768 + gc);
                            float2 r2 = *(const float2*)(res + (size_t)gr * N + gc);
                            vx = r2.x + g2.x * vx;
                            vy = r2.y + g2.y * vy;
                        }
                        *(float2*)(C + (size_t)gr * N + gc) = make_float2(vx, vy);
                    }
                }
            }
        }
    }
}

// ---------------- launch -------------------------------------------------------
static inline int cdiv(int a, int b) { return (a + b - 1) / b; }

extern "C" void kernel_launch(void* const* d_in, const int* in_sizes, int n_in,
                              void* d_out, int out_size) {
    const float* x      = (const float*)d_in[0];
    const void*  ei     = d_in[1];
    const float* c      = (const float*)d_in[2];
    const float* w_qkv  = (const float*)d_in[3];
    const float* w_proj = (const float*)d_in[4];
    const float* b_proj = (const float*)d_in[5];
    const float* w_mlp1 = (const float*)d_in[6];
    const float* b_mlp1 = (const float*)d_in[7];
    const float* w_mlp2 = (const float*)d_in[8];
    const float* b_mlp2 = (const float*)d_in[9];
    const float* w_ada  = (const float*)d_in[10];
    const float* b_ada  = (const float*)d_in[11];
    float*       out    = (float*)d_out;

    float *mods, *x1;
    __half *wthi, *xa, *ha, *qkvh;
    cudaGetSymbolAddress((void**)&mods, g_mods);
    cudaGetSymbolAddress((void**)&x1,   g_x1);
    cudaGetSymbolAddress((void**)&wthi, g_wthi);
    cudaGetSymbolAddress((void**)&xa,   g_xa);
    cudaGetSymbolAddress((void**)&ha,   g_ha);
    cudaGetSymbolAddress((void**)&qkvh, g_qkvh);

    cudaFuncSetAttribute(mma_gemm<0>, cudaFuncAttributeMaxDynamicSharedMemorySize, SM_TOT);
    cudaFuncSetAttribute(mma_gemm<2>, cudaFuncAttributeMaxDynamicSharedMemorySize, SM_TOT);
    cudaFuncSetAttribute(mma_gemm<3>, cudaFuncAttributeMaxDynamicSharedMemorySize, SM_TOT);
    cudaFuncSetAttribute(mma_gemm<4>, cudaFuncAttributeMaxDynamicSharedMemorySize, SM_TOT);

    const int MB = cdiv(NNODE, 128);

    detect_kernel<<<1, 256>>>(ei);                                                      // 0
    wsplit_all_kernel<<<cdiv(WTOT, 256), 256>>>(w_ada, w_qkv, w_proj, w_mlp1, w_mlp2);  // 1
    silu_h_kernel<<<cdiv(NNODE * HID / 4, 256), 256>>>(c, xa);                          // 2

    // mods = silu(c) @ w_ada + b_ada            [N, 768]    (launch idx 3: ncu slot)
    mma_gemm<0><<<dim3(768 / 128, MB), 256, SM_TOT>>>(
        xa, wthi + WOFF_ADA, b_ada, nullptr, nullptr, mods, nullptr, NNODE, 768, HID);

    // CSR build
    convert_kernel<<<cdiv(NEDGE, 256), 256>>>(ei);
    scan_kernel<<<1, 1024>>>();
    scatter_kernel<<<cdiv(NEDGE, 256), 256>>>();

    // xmod = modulate(LN(x), sh_msa, sc_msa) -> fp16
    ln_mod_kernel<<<cdiv(NNODE * 32, 256), 256>>>(x, 0, 128, xa);

    // qkv = xmod @ w_qkv -> fp16                 [N, 384]
    mma_gemm<4><<<dim3(384 / 128, MB), 256, SM_TOT>>>(
        xa, wthi + WOFF_QKV, nullptr, nullptr, nullptr, nullptr, qkvh, NNODE, 384, HID);

    // dst-major attention -> fp16 (reuse xa)
    dst_attn_kernel<<<cdiv(NNODE * 32, 256), 256>>>(xa);

    // x1 = x + g_msa * (attn @ w_proj + b_proj)
    mma_gemm<2><<<dim3(1, MB), 256, SM_TOT>>>(
        xa, wthi + WOFF_PROJ, b_proj, mods + 256, x, x1, nullptr, NNODE, HID, HID);

    // hmod = modulate(LN(x1), sh_mlp, sc_mlp) -> fp16 (reuse xa)
    ln_mod_kernel<<<cdiv(NNODE * 32, 256), 256>>>(x1, 384, 512, xa);

    // h = gelu(hmod @ w_mlp1 + b_mlp1) -> fp16   [N, 512]
    mma_gemm<3><<<dim3(MLPD / 128, MB), 256, SM_TOT>>>(
        xa, wthi + WOFF_MLP1, b_mlp1, nullptr, nullptr, nullptr, ha, NNODE, MLPD, HID);

    // out = x1 + g_mlp * (h @ w_mlp2 + b_mlp2)
    mma_gemm<2><<<dim3(1, MB), 256, SM_TOT>>>(
        ha, wthi + WOFF_MLP2, b_mlp2, mods + 640, x1, out, nullptr, NNODE, HID, MLPD);
}

// round 16
// speedup vs baseline: 1.8530x; 1.0167x over previous
#include <cuda_runtime.h>
#include <cuda_bf16.h>
#include <cuda_fp16.h>
#include <math_constants.h>
#include <cstdint>

#define HID  128
#define NNODE 50000
#define NEDGE 800000
#define MLPD 512

// ---------------- scratch (static device globals; no runtime alloc) ------------
__device__ __align__(16) float g_x1   [(size_t)NNODE * HID];
// fp16 buffers
__device__ __align__(16) __half g_modsh[(size_t)NNODE * 768];
__device__ __align__(16) __half g_qkvh[(size_t)NNODE * 384];
__device__ __align__(16) __half g_xa[(size_t)NNODE * HID];
__device__ __align__(16) __half g_ha[(size_t)NNODE * MLPD];
// CSR (dst-major) edge structure
__device__ int g_src[NEDGE];
__device__ int g_dst[NEDGE];
__device__ int g_psrc[NEDGE];
__device__ int g_cnt[NNODE];
__device__ int g_off[NNODE + 1];
__device__ int g_woff[NNODE];
__device__ int g_is32;

// transposed fp16 weights: WT[N][K], K contiguous
#define WOFF_ADA  0
#define WOFF_QKV  98304
#define WOFF_PROJ 147456
#define WOFF_MLP1 163840
#define WOFF_MLP2 229376
#define WTOT      294912
__device__ __align__(16) __half g_wthi[WTOT];

// ---------------- helpers ------------------------------------------------------
__device__ __forceinline__ float siluf(float v) {
    return v / (1.0f + __expf(-v));
}
__device__ __forceinline__ float gelu_tanh(float v) {
    float v3 = v * v * v;
    float t = tanhf(0.7978845608028654f * (v + 0.044715f * v3));
    return 0.5f * v * (1.0f + t);
}
__device__ __forceinline__ uint32_t smem_u32(const void* p) {
    uint32_t a;
    asm("{ .reg .u64 t; cvta.to.shared.u64 t, %1; cvt.u32.u64 %0, t; }" : "=r"(a) : "l"(p));
    return a;
}
__device__ __forceinline__ void ldsm4(uint32_t* r, uint32_t addr) {
    asm volatile("ldmatrix.sync.aligned.m8n8.x4.shared.b16 {%0,%1,%2,%3}, [%4];"
                 : "=r"(r[0]), "=r"(r[1]), "=r"(r[2]), "=r"(r[3]) : "r"(addr));
}
__device__ __forceinline__ void mma_fp16(float* d, const uint32_t* a,
                                         uint32_t b0, uint32_t b1) {
    asm volatile(
        "mma.sync.aligned.m16n8k16.row.col.f32.f16.f16.f32 "
        "{%0,%1,%2,%3}, {%4,%5,%6,%7}, {%8,%9}, {%0,%1,%2,%3};"
        : "+f"(d[0]), "+f"(d[1]), "+f"(d[2]), "+f"(d[3])
        : "r"(a[0]), "r"(a[1]), "r"(a[2]), "r"(a[3]), "r"(b0), "r"(b1));
}
__device__ __forceinline__ uint32_t pack_h2(float x, float y) {
    __half2 h = __floats2half2_rn(x, y);
    uint32_t r;
    memcpy(&r, &h, 4);
    return r;
}
__device__ __forceinline__ float2 ld_h2(const __half* p) {
    uint32_t u = *(const uint32_t*)p;
    __half2 h;
    memcpy(&h, &u, 4);
    return __half22float2(h);
}
__device__ __forceinline__ float4 ld_h4(const __half* p) {
    uint2 u = *(const uint2*)p;
    __half2 a, b;
    memcpy(&a, &u.x, 4);
    memcpy(&b, &u.y, 4);
    float2 fa = __half22float2(a), fb = __half22float2(b);
    return make_float4(fa.x, fa.y, fb.x, fb.y);
}
__device__ __forceinline__ void cpa16(uint32_t dst, const void* src, bool valid) {
    int sz = valid ? 16 : 0;
    asm volatile("cp.async.cg.shared.global [%0], [%1], 16, %2;"
                 :: "r"(dst), "l"(src), "r"(sz));
}

// ---------------- edge-index dtype detection + cnt zero ------------------------
__global__ void detect_kernel(const void* ei_raw) {
    const long long* p = (const long long*)ei_raw;
    int bad = 0;
    for (int i = threadIdx.x; i < 256; i += blockDim.x) {
        long long v = p[i];
        if (v < 0 || v >= NNODE) bad = 1;
    }
    bad = __syncthreads_or(bad);
    if (threadIdx.x == 0) g_is32 = bad;
    for (int i = threadIdx.x; i < NNODE; i += blockDim.x) g_cnt[i] = 0;
}

// ---------------- convert + dst histogram --------------------------------------
__global__ void convert_kernel(const void* ei_raw) {
    int e = blockIdx.x * blockDim.x + threadIdx.x;
    if (e >= NEDGE) return;
    int s, d;
    if (g_is32) {
        const int* p = (const int*)ei_raw;
        s = p[e]; d = p[NEDGE + e];
    } else {
        const long long* p = (const long long*)ei_raw;
        s = (int)p[e]; d = (int)p[NEDGE + e];
    }
    g_src[e] = s;
    g_dst[e] = d;
    atomicAdd(&g_cnt[d], 1);
}

// ---------------- single-block exclusive scan over g_cnt -----------------------
__global__ void scan_kernel() {
    const int tid  = threadIdx.x;
    const int lane = tid & 31, wid = tid >> 5;
    __shared__ int wsum[32];
    __shared__ int s_carry;
    if (tid == 0) s_carry = 0;
    __syncthreads();
    for (int base = 0; base < NNODE; base += 1024) {
        int i = base + tid;
        int v = (i < NNODE) ? g_cnt[i] : 0;
        int x = v;
        #pragma unroll
        for (int o = 1; o < 32; o <<= 1) {
            int t = __shfl_up_sync(0xffffffffu, x, o);
            if (lane >= o) x += t;
        }
        if (lane == 31) wsum[wid] = x;
        __syncthreads();
        if (wid == 0) {
            int y = wsum[lane];
            #pragma unroll
            for (int o = 1; o < 32; o <<= 1) {
                int t = __shfl_up_sync(0xffffffffu, y, o);
                if (lane >= o) y += t;
            }
            wsum[lane] = y;
        }
        __syncthreads();
        int warp_excl = (wid == 0) ? 0 : wsum[wid - 1];
        int incl = x + warp_excl;
        int carry = s_carry;
        if (i < NNODE) {
            g_off[i]  = carry + incl - v;
            g_woff[i] = carry + incl - v;
        }
        __syncthreads();
        if (tid == 1023) s_carry = carry + incl;
        __syncthreads();
    }
    if (tid == 0) g_off[NNODE] = s_carry;
}

// ---------------- scatter src ids into dst-major order -------------------------
__global__ void scatter_kernel() {
    int e = blockIdx.x * blockDim.x + threadIdx.x;
    if (e >= NEDGE) return;
    int pos = atomicAdd(&g_woff[g_dst[e]], 1);
    g_psrc[pos] = g_src[e];
}

// ---------------- ALL weight transposes -> fp16 in one kernel ------------------
__global__ void wsplit_all_kernel(const float* __restrict__ w_ada,
                                  const float* __restrict__ w_qkv,
                                  const float* __restrict__ w_proj,
                                  const float* __restrict__ w_mlp1,
                                  const float* __restrict__ w_mlp2) {
    int t = blockIdx.x * blockDim.x + threadIdx.x;
    if (t >= WTOT) return;
    const float* W;
    int Kg, Ng, l;
    if (t < WOFF_QKV)       { W = w_ada;  Kg = 128; Ng = 768; l = t - WOFF_ADA; }
    else if (t < WOFF_PROJ) { W = w_qkv;  Kg = 128; Ng = 384; l = t - WOFF_QKV; }
    else if (t < WOFF_MLP1) { W = w_proj; Kg = 128; Ng = 128; l = t - WOFF_PROJ; }
    else if (t < WOFF_MLP2) { W = w_mlp1; Kg = 128; Ng = 512; l = t - WOFF_MLP1; }
    else                    { W = w_mlp2; Kg = 512; Ng = 128; l = t - WOFF_MLP2; }
    int n = l / Kg, k = l % Kg;
    g_wthi[t] = __float2half_rn(W[(size_t)k * Ng + n]);
}

// ---------------- silu(c) -> fp16 ----------------------------------------------
__global__ void silu_h_kernel(const float* __restrict__ c,
                              __half* __restrict__ o) {
    int t4 = blockIdx.x * blockDim.x + threadIdx.x;
    if (t4 >= NNODE * HID / 4) return;
    float4 v = ((const float4*)c)[t4];
    uint32_t a = pack_h2(siluf(v.x), siluf(v.y));
    uint32_t b = pack_h2(siluf(v.z), siluf(v.w));
    *(uint2*)(o + (size_t)t4 * 4) = make_uint2(a, b);
}

// ---------------- LayerNorm + modulate (fp16 mods) -> fp16 ---------------------
__global__ void ln_mod_kernel(const float* __restrict__ X,
                              int shift_off, int scale_off,
                              __half* __restrict__ o) {
    int warp = (blockIdx.x * blockDim.x + threadIdx.x) >> 5;
    if (warp >= NNODE) return;
    int lane = threadIdx.x & 31;
    const float4 v = *(const float4*)(X + (size_t)warp * HID + lane * 4);
    float s  = v.x + v.y + v.z + v.w;
    float sq = v.x * v.x + v.y * v.y + v.z * v.z + v.w * v.w;
    #pragma unroll
    for (int oo = 16; oo > 0; oo >>= 1) {
        s  += __shfl_xor_sync(0xffffffffu, s,  oo);
        sq += __shfl_xor_sync(0xffffffffu, sq, oo);
    }
    float mean = s * (1.0f / HID);
    float var  = sq * (1.0f / HID) - mean * mean;
    float rstd = rsqrtf(var + 1e-6f);
    const float4 sh = ld_h4(g_modsh + (size_t)warp * 768 + shift_off + lane * 4);
    const float4 sc = ld_h4(g_modsh + (size_t)warp * 768 + scale_off + lane * 4);
    float ox = (v.x - mean) * rstd * (1.0f + sc.x) + sh.x;
    float oy = (v.y - mean) * rstd * (1.0f + sc.y) + sh.y;
    float oz = (v.z - mean) * rstd * (1.0f + sc.z) + sh.z;
    float ow = (v.w - mean) * rstd * (1.0f + sc.w) + sh.w;
    *(uint2*)(o + (size_t)warp * HID + lane * 4) =
        make_uint2(pack_h2(ox, oy), pack_h2(oz, ow));
}

// ---------------- dst-major attention (fp16 qkv, unroll x2) -> fp16 ------------
__global__ void dst_attn_kernel(__half* __restrict__ o) {
    int d = (blockIdx.x * blockDim.x + threadIdx.x) >> 5;
    if (d >= NNODE) return;
    int lane = threadIdx.x & 31;
    const float4 q = ld_h4(g_qkvh + (size_t)d * 384 + lane * 4);
    float4 acc = make_float4(0.f, 0.f, 0.f, 0.f);
    float den = 0.0f;
    const int b = g_off[d], e = g_off[d + 1];
    int i = b;
    for (; i + 2 <= e; i += 2) {
        int s0 = g_psrc[i], s1 = g_psrc[i + 1];
        const float4 k0 = ld_h4(g_qkvh + (size_t)s0 * 384 + 128 + lane * 4);
        const float4 v0 = ld_h4(g_qkvh + (size_t)s0 * 384 + 256 + lane * 4);
        const float4 k1 = ld_h4(g_qkvh + (size_t)s1 * 384 + 128 + lane * 4);
        const float4 v1 = ld_h4(g_qkvh + (size_t)s1 * 384 + 256 + lane * 4);
        float p0 = q.x * k0.x + q.y * k0.y + q.z * k0.z + q.w * k0.w;
        float p1 = q.x * k1.x + q.y * k1.y + q.z * k1.z + q.w * k1.w;
        p0 += __shfl_xor_sync(0xffffffffu, p0, 1);
        p1 += __shfl_xor_sync(0xffffffffu, p1, 1);
        p0 += __shfl_xor_sync(0xffffffffu, p0, 2);
        p1 += __shfl_xor_sync(0xffffffffu, p1, 2);
        float e0 = __expf(p0 * 0.25f);
        float e1 = __expf(p1 * 0.25f);
        acc.x += e0 * v0.x + e1 * v1.x;
        acc.y += e0 * v0.y + e1 * v1.y;
        acc.z += e0 * v0.z + e1 * v1.z;
        acc.w += e0 * v0.w + e1 * v1.w;
        den += e0 + e1;
    }
    if (i < e) {
        int s0 = g_psrc[i];
        const float4 k0 = ld_h4(g_qkvh + (size_t)s0 * 384 + 128 + lane * 4);
        const float4 v0 = ld_h4(g_qkvh + (size_t)s0 * 384 + 256 + lane * 4);
        float p0 = q.x * k0.x + q.y * k0.y + q.z * k0.z + q.w * k0.w;
        p0 += __shfl_xor_sync(0xffffffffu, p0, 1);
        p0 += __shfl_xor_sync(0xffffffffu, p0, 2);
        float e0 = __expf(p0 * 0.25f);
        acc.x += e0 * v0.x; acc.y += e0 * v0.y;
        acc.z += e0 * v0.z; acc.w += e0 * v0.w;
        den += e0;
    }
    float wn = (den > 0.0f) ? (1.0f / den) : 0.0f;
    *(uint2*)(o + (size_t)d * HID + lane * 4) =
        make_uint2(pack_h2(acc.x * wn, acc.y * wn), pack_h2(acc.z * wn, acc.w * wn));
}

// ---------------- fp16 mma.sync GEMM, 4-stage cp.async, templated K ------------
// A fp16 [M,K]; B fp16 [N,K].  fp32 accumulate.
// KK==128: all 4 chunks prefetched, ONE sync, no mid-loop barriers.
// EPI: 2=res+gate(fp16)*(acc+bias)->fp32  3=gelu->fp16  4=(+bias)->fp16
#define SLDA 40
#define STAGE_B 20480      // 2 * 128 * 40 * 2
#define SM_TOT  81920      // 4 stages
template<int EPI, int KK>
__global__ __launch_bounds__(256, 2)
void mma_gemm(const __half* __restrict__ Af,
              const __half* __restrict__ BT,
              const float* __restrict__ bias,
              const __half* __restrict__ gate,  // row stride 768 (EPI==2)
              const float* __restrict__ res,    // row stride N   (EPI==2)
              float* __restrict__ C,
              __half* __restrict__ Ch,          // EPI==3/4
              int M, int N) {
    extern __shared__ char smem[];
    const uint32_t sbase = smem_u32(smem);
    constexpr int nchunk = KK >> 5;

    const int tid  = threadIdx.x;
    const int lane = tid & 31;
    const int w    = tid >> 5;
    const int row0 = blockIdx.y * 128;
    const int col0 = blockIdx.x * 128;
    const int wr   = (w >> 1) * 32;
    const int wc   = (w & 1) * 64;

    float acc[2][8][4];
    #pragma unroll
    for (int i = 0; i < 2; i++)
        #pragma unroll
        for (int j = 0; j < 8; j++)
            #pragma unroll
            for (int q = 0; q < 4; q++) acc[i][j][q] = 0.0f;

    const int a_row_l = wr + (lane & 15);
    const int a_col_l = (lane >> 4) * 8;
    const int b_row_l = wc + ((lane >> 4) & 1) * 8 + (lane & 7);
    const int b_col_l = ((lane >> 3) & 1) * 8;

    const int cp_r0 = tid >> 2, cp_p = (tid & 3);

    auto prefetch = [&](int ch) {
        const int k0 = ch * 32;
        const uint32_t so = sbase + (uint32_t)(ch & 3) * STAGE_B;
        #pragma unroll
        for (int i = 0; i < 2; i++) {
            int r = cp_r0 + i * 64;
            int gr = row0 + r;
            bool ok = gr < M;
            const size_t arow = (size_t)(ok ? gr : 0) * KK + k0;
            uint32_t d = so + (uint32_t)(r * 80 + cp_p * 16);
            cpa16(d, (const char*)(Af + arow) + cp_p * 16, ok);
            const size_t brow = (size_t)(col0 + r) * KK + k0;
            cpa16(d + 10240, (const char*)(BT + brow) + cp_p * 16, true);
        }
        asm volatile("cp.async.commit_group;");
    };

    auto compute = [&](int ch) {
        const uint32_t so = sbase + (uint32_t)(ch & 3) * STAGE_B;
        #pragma unroll
        for (int ks = 0; ks < 2; ks++) {
            uint32_t ah[2][4];
            #pragma unroll
            for (int mt = 0; mt < 2; mt++) {
                uint32_t off = so + (uint32_t)(((a_row_l + mt * 16) * SLDA + a_col_l + ks * 16) * 2);
                ldsm4(ah[mt], off);
            }
            #pragma unroll
            for (int np = 0; np < 4; np++) {
                uint32_t bh[4];
                uint32_t off = so + 10240 + (uint32_t)(((b_row_l + np * 16) * SLDA + b_col_l + ks * 16) * 2);
                ldsm4(bh, off);
                #pragma unroll
                for (int mt = 0; mt < 2; mt++) {
                    mma_fp16(acc[mt][np * 2],     ah[mt], bh[0], bh[1]);
                    mma_fp16(acc[mt][np * 2 + 1], ah[mt], bh[2], bh[3]);
                }
            }
        }
    };

    if (KK == 128) {
        // all four chunks in flight, single barrier, zero mid-loop syncs
        #pragma unroll
        for (int ch = 0; ch < 4; ch++) prefetch(ch);
        asm volatile("cp.async.wait_group 0;");
        __syncthreads();
        #pragma unroll
        for (int ch = 0; ch < 4; ch++) compute(ch);
    } else {
        prefetch(0); prefetch(1); prefetch(2);
        for (int ch = 0; ch < nchunk; ch++) {
            if (ch + 3 < nchunk) {
                prefetch(ch + 3);
                asm volatile("cp.async.wait_group 3;");
            } else if (ch + 2 < nchunk) {
                asm volatile("cp.async.wait_group 2;");
            } else if (ch + 1 < nchunk) {
                asm volatile("cp.async.wait_group 1;");
            } else {
                asm volatile("cp.async.wait_group 0;");
            }
            __syncthreads();
            compute(ch);
            __syncthreads();
        }
    }

    // ---- epilogue ----
    #pragma unroll
    for (int mt = 0; mt < 2; mt++) {
        #pragma unroll
        for (int nt = 0; nt < 8; nt++) {
            int gc = col0 + wc + nt * 8 + (lane & 3) * 2;
            #pragma unroll
            for (int g = 0; g < 2; g++) {
                int gr = row0 + wr + mt * 16 + (lane >> 2) + g * 8;
                if (gr < M) {
                    float vx = acc[mt][nt][g * 2];
                    float vy = acc[mt][nt][g * 2 + 1];
                    if (bias != nullptr) {
                        float2 b2 = *(const float2*)(bias + gc);
                        vx += b2.x; vy += b2.y;
                    }
                    if (EPI == 3 || EPI == 4) {
                        if (EPI == 3) { vx = gelu_tanh(vx); vy = gelu_tanh(vy); }
                        *(uint32_t*)(Ch + (size_t)gr * N + gc) = pack_h2(vx, vy);
                    } else {
                        if (EPI == 2) {
                            float2 g2 = ld_h2(gate + (size_t)gr * 768 + gc);
                            float2 r2 = *(const float2*)(res + (size_t)gr * N + gc);
                            vx = r2.x + g2.x * vx;
                            vy = r2.y + g2.y * vy;
                        }
                        *(float2*)(C + (size_t)gr * N + gc) = make_float2(vx, vy);
                    }
                }
            }
        }
    }
}

// ---------------- launch -------------------------------------------------------
static inline int cdiv(int a, int b) { return (a + b - 1) / b; }

extern "C" void kernel_launch(void* const* d_in, const int* in_sizes, int n_in,
                              void* d_out, int out_size) {
    const float* x      = (const float*)d_in[0];
    const void*  ei     = d_in[1];
    const float* c      = (const float*)d_in[2];
    const float* w_qkv  = (const float*)d_in[3];
    const float* w_proj = (const float*)d_in[4];
    const float* b_proj = (const float*)d_in[5];
    const float* w_mlp1 = (const float*)d_in[6];
    const float* b_mlp1 = (const float*)d_in[7];
    const float* w_mlp2 = (const float*)d_in[8];
    const float* b_mlp2 = (const float*)d_in[9];
    const float* w_ada  = (const float*)d_in[10];
    const float* b_ada  = (const float*)d_in[11];
    float*       out    = (float*)d_out;

    float *x1;
    __half *wthi, *xa, *ha, *qkvh, *modsh;
    cudaGetSymbolAddress((void**)&x1,    g_x1);
    cudaGetSymbolAddress((void**)&wthi,  g_wthi);
    cudaGetSymbolAddress((void**)&xa,    g_xa);
    cudaGetSymbolAddress((void**)&ha,    g_ha);
    cudaGetSymbolAddress((void**)&qkvh,  g_qkvh);
    cudaGetSymbolAddress((void**)&modsh, g_modsh);

    cudaFuncSetAttribute(mma_gemm<2, 128>, cudaFuncAttributeMaxDynamicSharedMemorySize, SM_TOT);
    cudaFuncSetAttribute(mma_gemm<3, 128>, cudaFuncAttributeMaxDynamicSharedMemorySize, SM_TOT);
    cudaFuncSetAttribute(mma_gemm<4, 128>, cudaFuncAttributeMaxDynamicSharedMemorySize, SM_TOT);
    cudaFuncSetAttribute(mma_gemm<2, 512>, cudaFuncAttributeMaxDynamicSharedMemorySize, SM_TOT);

    const int MB = cdiv(NNODE, 128);

    detect_kernel<<<1, 256>>>(ei);                                                      // 0
    wsplit_all_kernel<<<cdiv(WTOT, 256), 256>>>(w_ada, w_qkv, w_proj, w_mlp1, w_mlp2);  // 1
    silu_h_kernel<<<cdiv(NNODE * HID / 4, 256), 256>>>(c, xa);                          // 2

    // mods = silu(c) @ w_ada + b_ada -> fp16     [N, 768]   (launch idx 3: ncu slot)
    mma_gemm<4, 128><<<dim3(768 / 128, MB), 256, SM_TOT>>>(
        xa, wthi + WOFF_ADA, b_ada, nullptr, nullptr, nullptr, modsh, NNODE, 768);

    // CSR build
    convert_kernel<<<cdiv(NEDGE, 256), 256>>>(ei);
    scan_kernel<<<1, 1024>>>();
    scatter_kernel<<<cdiv(NEDGE, 256), 256>>>();

    // xmod = modulate(LN(x), sh_msa, sc_msa) -> fp16
    ln_mod_kernel<<<cdiv(NNODE * 32, 256), 256>>>(x, 0, 128, xa);

    // qkv = xmod @ w_qkv -> fp16                 [N, 384]
    mma_gemm<4, 128><<<dim3(384 / 128, MB), 256, SM_TOT>>>(
        xa, wthi + WOFF_QKV, nullptr, nullptr, nullptr, nullptr, qkvh, NNODE, 384);

    // dst-major attention -> fp16 (reuse xa)
    dst_attn_kernel<<<cdiv(NNODE * 32, 256), 256>>>(xa);

    // x1 = x + g_msa * (attn @ w_proj + b_proj)
    mma_gemm<2, 128><<<dim3(1, MB), 256, SM_TOT>>>(
        xa, wthi + WOFF_PROJ, b_proj, modsh + 256, x, x1, nullptr, NNODE, HID);

    // hmod = modulate(LN(x1), sh_mlp, sc_mlp) -> fp16 (reuse xa)
    ln_mod_kernel<<<cdiv(NNODE * 32, 256), 256>>>(x1, 384, 512, xa);

    // h = gelu(hmod @ w_mlp1 + b_mlp1) -> fp16   [N, 512]
    mma_gemm<3, 128><<<dim3(MLPD / 128, MB), 256, SM_TOT>>>(
        xa, wthi + WOFF_MLP1, b_mlp1, nullptr, nullptr, nullptr, ha, NNODE, MLPD);

    // out = x1 + g_mlp * (h @ w_mlp2 + b_mlp2)
    mma_gemm<2, 512><<<dim3(1, MB), 256, SM_TOT>>>(
        ha, wthi + WOFF_MLP2, b_mlp2, modsh + 640, x1, out, nullptr, NNODE, HID);
}